// round 9
// baseline (speedup 1.0000x reference)
#include <cuda_runtime.h>
#include <cuda_fp16.h>
#include <math.h>
#include <stdint.h>

#define D 128
#define GAMMA 0.1f
#define EPS 0.1f
#define MAXN 100000
#define MAXE 1600000
#define SCAN_BS 1024
#define MAXB ((MAXN + SCAN_BS - 1) / SCAN_BS)

// ---------------- scratch (static device globals; no allocation) ----------------
__device__ __align__(32) __half g_xh[MAXN * 256];    // row: [xa (128) | xw (128)] fp16, 512B/row
__device__ __align__(16) float  g_xbuf[MAXN * D];    // ping-pong x buffer
__device__ __align__(16) float  g_wcat[256 * D];     // row j<128: A row j; j>=128: Wphi row j-128
__device__ int   g_deg[MAXN];
__device__ float g_dinv[MAXN];
__device__ int   g_rowptr[MAXN + 1];
__device__ int   g_wptr[MAXN];
__device__ __align__(8) int2 g_edge[MAXE];           // .x = src col, .y = norm (float bits)
__device__ int   g_bsums[MAXB + 2];
__device__ int   g_boff[MAXB + 2];

__device__ __forceinline__ float tanh_fast(float x) {
    float r;
    asm("tanh.approx.f32 %0, %1;" : "=f"(r) : "f"(x));
    return r;
}

// 256-bit gather with L2 evict-last (ptxas requires v4.b64 width for the hint)
__device__ __forceinline__ void ldg_el_256(const __half* p, uint64_t r[4]) {
    asm volatile("ld.global.nc.L2::evict_last.v4.u64 {%0,%1,%2,%3}, [%4];"
                 : "=l"(r[0]), "=l"(r[1]), "=l"(r[2]), "=l"(r[3]) : "l"(p));
}

// ---------------- prep: build concatenated weight (row-major [j][k]) ----------------
__global__ void prep_weights(const float* __restrict__ W, const float* __restrict__ Wphi) {
    int idx = blockIdx.x * blockDim.x + threadIdx.x;
    if (idx >= 256 * D) return;
    int j = idx / D;
    int k = idx % D;
    float v;
    if (j < D) {
        v = W[j * D + k] - W[k * D + j];
        if (j == k) v -= GAMMA;
    } else {
        v = Wphi[(j - D) * D + k];
    }
    g_wcat[j * D + k] = v;
}

// ---------------- degree ----------------
__global__ void zero_deg(int n) {
    int i = blockIdx.x * blockDim.x + threadIdx.x;
    if (i < n) g_deg[i] = 0;
}
__global__ void count_deg(const int* __restrict__ ei, int e) {
    int idx = blockIdx.x * blockDim.x + threadIdx.x;
    if (idx >= e) return;
    atomicAdd(&g_deg[ei[e + idx]], 1);
}

// ---------------- exclusive scan of deg -> rowptr ----------------
__global__ void scan1(int n) {
    __shared__ int sh[SCAN_BS];
    int tx = threadIdx.x;
    int i = blockIdx.x * SCAN_BS + tx;
    int v = (i < n) ? g_deg[i] : 0;
    sh[tx] = v;
    __syncthreads();
    for (int off = 1; off < SCAN_BS; off <<= 1) {
        int t = (tx >= off) ? sh[tx - off] : 0;
        __syncthreads();
        sh[tx] += t;
        __syncthreads();
    }
    int incl = sh[tx];
    if (i < n) g_rowptr[i] = incl - v;
    if (tx == SCAN_BS - 1) g_bsums[blockIdx.x] = incl;
}
__global__ void scan2(int nb, int e_total, int n) {
    int run = 0;
    for (int b = 0; b < nb; b++) { g_boff[b] = run; run += g_bsums[b]; }
    g_rowptr[n] = e_total;
}
// scan3 also computes dinv (deg already loaded here)
__global__ void scan3(int n) {
    int i = blockIdx.x * blockDim.x + threadIdx.x;
    if (i >= n) return;
    int v = g_rowptr[i] + g_boff[i / SCAN_BS];
    g_rowptr[i] = v;
    g_wptr[i] = v;
    g_dinv[i] = rsqrtf((float)g_deg[i] + 1.0f);
}
__global__ void fill_csr(const int* __restrict__ ei, int e) {
    int idx = blockIdx.x * blockDim.x + threadIdx.x;
    if (idx >= e) return;
    int src = ei[idx];
    int dst = ei[e + idx];
    int pos = atomicAdd(&g_wptr[dst], 1);
    float nrm = g_dinv[src] * g_dinv[dst];
    g_edge[pos] = make_int2(src, __float_as_int(nrm));
}

// ---------------- tf32 mma.sync GEMM (persistent): [xa | xw] = x @ wcat^T ----------------
#define GT 512
#define LDP 132
#define GEMM_SMEM ((128 * LDP + 256 * LDP) * 4)

__device__ __forceinline__ uint32_t f2tf32(float f) {
    uint32_t u;
    asm("cvt.rna.tf32.f32 %0, %1;" : "=r"(u) : "f"(f));
    return u;
}

__global__ __launch_bounds__(GT, 1) void gemm_mma(const float* __restrict__ xin, int n, int tiles) {
    extern __shared__ float sm[];
    float* As = sm;               // 128 x 132
    float* Bs = sm + 128 * LDP;   // 256 x 132

    int tid = threadIdx.x;
    int wid = tid >> 5;
    int lane = tid & 31;

    // load B (weights) ONCE, tf32-rounded (RNA)
    for (int i = tid; i < 256 * 32; i += GT) {
        int j = i >> 5, c4 = i & 31;
        float4 v = ((const float4*)g_wcat)[i];
        float* dst = Bs + j * LDP + c4 * 4;
        dst[0] = __uint_as_float(f2tf32(v.x));
        dst[1] = __uint_as_float(f2tf32(v.y));
        dst[2] = __uint_as_float(f2tf32(v.z));
        dst[3] = __uint_as_float(f2tf32(v.w));
    }

    int wm = wid >> 2;
    int wn = wid & 3;
    int grp = lane >> 2;
    int tig = lane & 3;

    uint32_t As_base = (uint32_t)__cvta_generic_to_shared(As);

    const float* Abase = As + (wm * 32 + grp) * LDP + tig;
    const float* Bbase = Bs + (wn * 64 + grp) * LDP + tig;
    int gcolBase = (wn >= 2 ? 128 : 0) + (wn & 1) * 64 + 2 * tig;

    for (int t = blockIdx.x; t < tiles; t += gridDim.x) {
        int rowBase = t << 7;

        __syncthreads();

        // async-load A tile: 128 rows x 128 cols fp32 (zero-fill OOB rows)
#pragma unroll
        for (int i = tid; i < 4096; i += GT) {
            int r = i >> 5, c4 = i & 31;
            int row = rowBase + r;
            uint32_t daddr = As_base + (uint32_t)(r * LDP + c4 * 4) * 4u;
            const float* src = xin + (size_t)row * D + c4 * 4;
            int sz = (row < n) ? 16 : 0;
            asm volatile("cp.async.ca.shared.global [%0], [%1], 16, %2;"
                         :: "r"(daddr), "l"(src), "r"(sz));
        }
        asm volatile("cp.async.commit_group;");
        asm volatile("cp.async.wait_group 0;");
        __syncthreads();

        float c[2][8][4];
#pragma unroll
        for (int mt = 0; mt < 2; mt++)
#pragma unroll
            for (int nt = 0; nt < 8; nt++)
#pragma unroll
                for (int q = 0; q < 4; q++) c[mt][nt][q] = 0.f;

#pragma unroll
        for (int ks = 0; ks < 16; ks++) {
            int k0 = ks * 8;
            uint32_t a[2][4], b[8][2];
#pragma unroll
            for (int mt = 0; mt < 2; mt++) {
                const float* ap = Abase + mt * 16 * LDP + k0;
                a[mt][0] = __float_as_uint(ap[0]);
                a[mt][1] = __float_as_uint(ap[8 * LDP]);
                a[mt][2] = __float_as_uint(ap[4]);
                a[mt][3] = __float_as_uint(ap[8 * LDP + 4]);
            }
#pragma unroll
            for (int nt = 0; nt < 8; nt++) {
                const float* bp = Bbase + nt * 8 * LDP + k0;
                b[nt][0] = __float_as_uint(bp[0]);
                b[nt][1] = __float_as_uint(bp[4]);
            }
#pragma unroll
            for (int mt = 0; mt < 2; mt++) {
#pragma unroll
                for (int nt = 0; nt < 8; nt++) {
                    asm volatile(
                        "mma.sync.aligned.m16n8k8.row.col.f32.tf32.tf32.f32 "
                        "{%0,%1,%2,%3}, {%4,%5,%6,%7}, {%8,%9}, {%0,%1,%2,%3};"
                        : "+f"(c[mt][nt][0]), "+f"(c[mt][nt][1]),
                          "+f"(c[mt][nt][2]), "+f"(c[mt][nt][3])
                        : "r"(a[mt][0]), "r"(a[mt][1]), "r"(a[mt][2]), "r"(a[mt][3]),
                          "r"(b[nt][0]), "r"(b[nt][1]));
                }
            }
        }

        // epilogue: fp16 into combined [xa | xw] row
#pragma unroll
        for (int mt = 0; mt < 2; mt++) {
            int r0 = rowBase + wm * 32 + mt * 16 + grp;
            int r1 = r0 + 8;
#pragma unroll
            for (int nt = 0; nt < 8; nt++) {
                int gcol = gcolBase + nt * 8;
                if (r0 < n)
                    *(__half2*)(g_xh + (size_t)r0 * 256 + gcol) =
                        __floats2half2_rn(c[mt][nt][0], c[mt][nt][1]);
                if (r1 < n)
                    *(__half2*)(g_xh + (size_t)r1 * 256 + gcol) =
                        __floats2half2_rn(c[mt][nt][2], c[mt][nt][3]);
            }
        }
    }
}

// ---------------- fused aggregate + update (LDG.256 quad gather, evict_last) ----------------
// one warp per node; 8 lanes cover a 256B xw half-row (32B each); 4 edges per warp-LDG.256
__global__ __launch_bounds__(256) void agg_update(const float* __restrict__ xin,
                                                  float* __restrict__ xout,
                                                  const float* __restrict__ bias,
                                                  int n) {
    int node = (blockIdx.x * blockDim.x + threadIdx.x) >> 5;
    int lane = threadIdx.x & 31;
    if (node >= n) return;

    int start = g_rowptr[node];
    int end = g_rowptr[node + 1];

    int sub3 = lane & 7;     // 32B chunk within xw half-row (8 x 32B = 256B)
    int quad = lane >> 3;    // which edge of a group of 4

    float acc[16];
#pragma unroll
    for (int q = 0; q < 16; q++) acc[q] = 0.f;

    for (int j = start; j < end; j += 32) {
        int cnt = min(32, end - j);
        int c = 0;
        float w = 0.f;
        if (lane < cnt) {
            int2 eb = __ldg(&g_edge[j + lane]);
            c = eb.x;
            w = __int_as_float(eb.y);
        }
        int nb = (cnt + 7) >> 3;     // batches of 8 edges, zero-padded
        for (int b = 0; b < nb; b++) {
            int t = b * 8;
            int s0 = t + quad;
            int s1 = t + 4 + quad;
            int c0 = __shfl_sync(0xFFFFFFFFu, c, s0);
            float w0 = __shfl_sync(0xFFFFFFFFu, w, s0);
            int c1 = __shfl_sync(0xFFFFFFFFu, c, s1);
            float w1 = __shfl_sync(0xFFFFFFFFu, w, s1);
            if (s0 >= cnt) { c0 = 0; w0 = 0.f; }
            if (s1 >= cnt) { c1 = 0; w1 = 0.f; }

            uint64_t u0[4], u1[4];
            ldg_el_256(g_xh + (size_t)c0 * 256 + 128 + sub3 * 16, u0);
            ldg_el_256(g_xh + (size_t)c1 * 256 + 128 + sub3 * 16, u1);

#pragma unroll
            for (int q = 0; q < 4; q++) {
                __half2* h = (__half2*)&u0[q];
                float2 f0 = __half22float2(h[0]);
                float2 f1 = __half22float2(h[1]);
                acc[q * 4 + 0] += w0 * f0.x;
                acc[q * 4 + 1] += w0 * f0.y;
                acc[q * 4 + 2] += w0 * f1.x;
                acc[q * 4 + 3] += w0 * f1.y;
            }
#pragma unroll
            for (int q = 0; q < 4; q++) {
                __half2* h = (__half2*)&u1[q];
                float2 f0 = __half22float2(h[0]);
                float2 f1 = __half22float2(h[1]);
                acc[q * 4 + 0] += w1 * f0.x;
                acc[q * 4 + 1] += w1 * f0.y;
                acc[q * 4 + 2] += w1 * f1.x;
                acc[q * 4 + 3] += w1 * f1.y;
            }
        }
    }

    // reduce across the 4 quads (same sub3)
#pragma unroll
    for (int q = 0; q < 16; q++) {
        acc[q] += __shfl_xor_sync(0xFFFFFFFFu, acc[q], 8);
        acc[q] += __shfl_xor_sync(0xFFFFFFFFu, acc[q], 16);
    }

    // epilogue: lanes 0..7 (quad==0) own 16 cols each (cols sub3*16 .. +15)
    if (quad == 0) {
        float dv = g_dinv[node];
        float d2 = dv * dv;

        uint64_t ua[4], us[4];
        ldg_el_256(g_xh + (size_t)node * 256 + sub3 * 16, ua);        // xa
        ldg_el_256(g_xh + (size_t)node * 256 + 128 + sub3 * 16, us);  // xw self

        float xa[16], self[16];
#pragma unroll
        for (int q = 0; q < 4; q++) {
            __half2* ha = (__half2*)&ua[q];
            __half2* hs = (__half2*)&us[q];
            float2 a0 = __half22float2(ha[0]);
            float2 a1 = __half22float2(ha[1]);
            float2 s0 = __half22float2(hs[0]);
            float2 s1 = __half22float2(hs[1]);
            xa[q * 4 + 0] = a0.x; xa[q * 4 + 1] = a0.y;
            xa[q * 4 + 2] = a1.x; xa[q * 4 + 3] = a1.y;
            self[q * 4 + 0] = s0.x; self[q * 4 + 1] = s0.y;
            self[q * 4 + 2] = s1.x; self[q * 4 + 3] = s1.y;
        }

        const float4* xv4 = (const float4*)(xin + (size_t)node * D) + sub3 * 4;
        const float4* bv4 = (const float4*)bias + sub3 * 4;
        float4* out4 = (float4*)(xout + (size_t)node * D) + sub3 * 4;

#pragma unroll
        for (int h = 0; h < 4; h++) {
            float4 xv = __ldg(&xv4[h]);
            float4 bv = __ldg(&bv4[h]);
            float4 o;
            o.x = xv.x + EPS * tanh_fast(xa[h * 4 + 0] + acc[h * 4 + 0] + self[h * 4 + 0] * d2 + bv.x);
            o.y = xv.y + EPS * tanh_fast(xa[h * 4 + 1] + acc[h * 4 + 1] + self[h * 4 + 1] * d2 + bv.y);
            o.z = xv.z + EPS * tanh_fast(xa[h * 4 + 2] + acc[h * 4 + 2] + self[h * 4 + 2] * d2 + bv.z);
            o.w = xv.w + EPS * tanh_fast(xa[h * 4 + 3] + acc[h * 4 + 3] + self[h * 4 + 3] * d2 + bv.w);
            out4[h] = o;
        }
    }
}

// ---------------- launch ----------------
extern "C" void kernel_launch(void* const* d_in, const int* in_sizes, int n_in,
                              void* d_out, int out_size) {
    const float* x0   = (const float*)d_in[0];
    const int*   ei   = (const int*)d_in[1];
    const float* W    = (const float*)d_in[2];
    const float* Wphi = (const float*)d_in[3];
    const float* bias = (const float*)d_in[4];

    int n = in_sizes[0] / D;
    int e = in_sizes[1] / 2;
    if (n > MAXN) n = MAXN;
    if (e > MAXE) e = MAXE;

    float* xbuf = nullptr;
    cudaGetSymbolAddress((void**)&xbuf, g_xbuf);
    float* outp = (float*)d_out;

    cudaFuncSetAttribute(gemm_mma, cudaFuncAttributeMaxDynamicSharedMemorySize, GEMM_SMEM);

    // one-time graph preprocessing
    prep_weights<<<(256 * D + 255) / 256, 256>>>(W, Wphi);
    zero_deg<<<(n + 255) / 256, 256>>>(n);
    count_deg<<<(e + 255) / 256, 256>>>(ei, e);
    int nb = (n + SCAN_BS - 1) / SCAN_BS;
    scan1<<<nb, SCAN_BS>>>(n);
    scan2<<<1, 1>>>(nb, e, n);
    scan3<<<(n + 255) / 256, 256>>>(n);
    fill_csr<<<(e + 255) / 256, 256>>>(ei, e);

    // 4 iterations, ping-pong: x0 -> xbuf -> d_out -> xbuf -> d_out
    const float* xin = x0;
    int tiles = (n + 127) >> 7;
    for (int it = 0; it < 4; it++) {
        float* xout = (it % 2 == 0) ? xbuf : outp;
        gemm_mma<<<148, GT, GEMM_SMEM>>>(xin, n, tiles);
        agg_update<<<(n + 7) / 8, 256>>>(xin, xout, bias, n);
        xin = xout;
    }
}

// round 10
// speedup vs baseline: 1.1045x; 1.1045x over previous
#include <cuda_runtime.h>
#include <cuda_fp16.h>
#include <math.h>
#include <stdint.h>

#define D 128
#define GAMMA 0.1f
#define EPS 0.1f
#define MAXN 100000
#define MAXE 1600000
#define SCAN_BS 1024
#define MAXB ((MAXN + SCAN_BS - 1) / SCAN_BS)

// ---------------- scratch (static device globals; no allocation) ----------------
__device__ __align__(16) __half g_xh[MAXN * 256];    // row: [xa (128) | xw (128)] fp16
__device__ __align__(16) float  g_xbuf[MAXN * D];    // ping-pong x buffer
__device__ __align__(16) float  g_wcat[256 * D];     // row j<128: A row j; j>=128: Wphi row j-128
__device__ int   g_deg[MAXN];
__device__ float g_dinv[MAXN];
__device__ int   g_rowptr[MAXN + 1];
__device__ int   g_wptr[MAXN];
__device__ __align__(8) int2 g_edge[MAXE];           // .x = src col, .y = norm (float bits)
__device__ int   g_bsums[MAXB + 2];
__device__ int   g_boff[MAXB + 2];

__device__ __forceinline__ float tanh_fast(float x) {
    float r;
    asm("tanh.approx.f32 %0, %1;" : "=f"(r) : "f"(x));
    return r;
}

// ---------------- prep: build concatenated weight (row-major [j][k]) ----------------
__global__ void prep_weights(const float* __restrict__ W, const float* __restrict__ Wphi) {
    int idx = blockIdx.x * blockDim.x + threadIdx.x;
    if (idx >= 256 * D) return;
    int j = idx / D;
    int k = idx % D;
    float v;
    if (j < D) {
        v = W[j * D + k] - W[k * D + j];
        if (j == k) v -= GAMMA;
    } else {
        v = Wphi[(j - D) * D + k];
    }
    g_wcat[j * D + k] = v;
}

// ---------------- degree ----------------
__global__ void zero_deg(int n) {
    int i = blockIdx.x * blockDim.x + threadIdx.x;
    if (i < n) g_deg[i] = 0;
}
__global__ void count_deg(const int* __restrict__ ei, int e) {
    int idx = blockIdx.x * blockDim.x + threadIdx.x;
    if (idx >= e) return;
    atomicAdd(&g_deg[ei[e + idx]], 1);
}

// ---------------- exclusive scan of deg -> rowptr ----------------
__global__ void scan1(int n) {
    __shared__ int sh[SCAN_BS];
    int tx = threadIdx.x;
    int i = blockIdx.x * SCAN_BS + tx;
    int v = (i < n) ? g_deg[i] : 0;
    sh[tx] = v;
    __syncthreads();
    for (int off = 1; off < SCAN_BS; off <<= 1) {
        int t = (tx >= off) ? sh[tx - off] : 0;
        __syncthreads();
        sh[tx] += t;
        __syncthreads();
    }
    int incl = sh[tx];
    if (i < n) g_rowptr[i] = incl - v;
    if (tx == SCAN_BS - 1) g_bsums[blockIdx.x] = incl;
}
__global__ void scan2(int nb, int e_total, int n) {
    int run = 0;
    for (int b = 0; b < nb; b++) { g_boff[b] = run; run += g_bsums[b]; }
    g_rowptr[n] = e_total;
}
// scan3 also computes dinv (deg already loaded here)
__global__ void scan3(int n) {
    int i = blockIdx.x * blockDim.x + threadIdx.x;
    if (i >= n) return;
    int v = g_rowptr[i] + g_boff[i / SCAN_BS];
    g_rowptr[i] = v;
    g_wptr[i] = v;
    g_dinv[i] = rsqrtf((float)g_deg[i] + 1.0f);
}
__global__ void fill_csr(const int* __restrict__ ei, int e) {
    int idx = blockIdx.x * blockDim.x + threadIdx.x;
    if (idx >= e) return;
    int src = ei[idx];
    int dst = ei[e + idx];
    int pos = atomicAdd(&g_wptr[dst], 1);
    float nrm = g_dinv[src] * g_dinv[dst];
    g_edge[pos] = make_int2(src, __float_as_int(nrm));
}

// ---------------- tf32 mma.sync GEMM (persistent): [xa | xw] = x @ wcat^T ----------------
#define GT 512
#define LDP 132
#define GEMM_SMEM ((128 * LDP + 256 * LDP) * 4)

__device__ __forceinline__ uint32_t f2tf32(float f) {
    uint32_t u;
    asm("cvt.rna.tf32.f32 %0, %1;" : "=r"(u) : "f"(f));
    return u;
}

__global__ __launch_bounds__(GT, 1) void gemm_mma(const float* __restrict__ xin, int n, int tiles) {
    extern __shared__ float sm[];
    float* As = sm;               // 128 x 132
    float* Bs = sm + 128 * LDP;   // 256 x 132

    int tid = threadIdx.x;
    int wid = tid >> 5;
    int lane = tid & 31;

    // load B (weights) ONCE, tf32-rounded (RNA)
    for (int i = tid; i < 256 * 32; i += GT) {
        int j = i >> 5, c4 = i & 31;
        float4 v = ((const float4*)g_wcat)[i];
        float* dst = Bs + j * LDP + c4 * 4;
        dst[0] = __uint_as_float(f2tf32(v.x));
        dst[1] = __uint_as_float(f2tf32(v.y));
        dst[2] = __uint_as_float(f2tf32(v.z));
        dst[3] = __uint_as_float(f2tf32(v.w));
    }

    int wm = wid >> 2;
    int wn = wid & 3;
    int grp = lane >> 2;
    int tig = lane & 3;

    uint32_t As_base = (uint32_t)__cvta_generic_to_shared(As);

    const float* Abase = As + (wm * 32 + grp) * LDP + tig;
    const float* Bbase = Bs + (wn * 64 + grp) * LDP + tig;
    int gcolBase = (wn >= 2 ? 128 : 0) + (wn & 1) * 64 + 2 * tig;

    for (int t = blockIdx.x; t < tiles; t += gridDim.x) {
        int rowBase = t << 7;

        __syncthreads();

        // async-load A tile: 128 rows x 128 cols fp32 (zero-fill OOB rows)
#pragma unroll
        for (int i = tid; i < 4096; i += GT) {
            int r = i >> 5, c4 = i & 31;
            int row = rowBase + r;
            uint32_t daddr = As_base + (uint32_t)(r * LDP + c4 * 4) * 4u;
            const float* src = xin + (size_t)row * D + c4 * 4;
            int sz = (row < n) ? 16 : 0;
            asm volatile("cp.async.ca.shared.global [%0], [%1], 16, %2;"
                         :: "r"(daddr), "l"(src), "r"(sz));
        }
        asm volatile("cp.async.commit_group;");
        asm volatile("cp.async.wait_group 0;");
        __syncthreads();

        float c[2][8][4];
#pragma unroll
        for (int mt = 0; mt < 2; mt++)
#pragma unroll
            for (int nt = 0; nt < 8; nt++)
#pragma unroll
                for (int q = 0; q < 4; q++) c[mt][nt][q] = 0.f;

#pragma unroll
        for (int ks = 0; ks < 16; ks++) {
            int k0 = ks * 8;
            uint32_t a[2][4], b[8][2];
#pragma unroll
            for (int mt = 0; mt < 2; mt++) {
                const float* ap = Abase + mt * 16 * LDP + k0;
                a[mt][0] = __float_as_uint(ap[0]);
                a[mt][1] = __float_as_uint(ap[8 * LDP]);
                a[mt][2] = __float_as_uint(ap[4]);
                a[mt][3] = __float_as_uint(ap[8 * LDP + 4]);
            }
#pragma unroll
            for (int nt = 0; nt < 8; nt++) {
                const float* bp = Bbase + nt * 8 * LDP + k0;
                b[nt][0] = __float_as_uint(bp[0]);
                b[nt][1] = __float_as_uint(bp[4]);
            }
#pragma unroll
            for (int mt = 0; mt < 2; mt++) {
#pragma unroll
                for (int nt = 0; nt < 8; nt++) {
                    asm volatile(
                        "mma.sync.aligned.m16n8k8.row.col.f32.tf32.tf32.f32 "
                        "{%0,%1,%2,%3}, {%4,%5,%6,%7}, {%8,%9}, {%0,%1,%2,%3};"
                        : "+f"(c[mt][nt][0]), "+f"(c[mt][nt][1]),
                          "+f"(c[mt][nt][2]), "+f"(c[mt][nt][3])
                        : "r"(a[mt][0]), "r"(a[mt][1]), "r"(a[mt][2]), "r"(a[mt][3]),
                          "r"(b[nt][0]), "r"(b[nt][1]));
                }
            }
        }

        // epilogue: fp16 into combined [xa | xw] row
#pragma unroll
        for (int mt = 0; mt < 2; mt++) {
            int r0 = rowBase + wm * 32 + mt * 16 + grp;
            int r1 = r0 + 8;
#pragma unroll
            for (int nt = 0; nt < 8; nt++) {
                int gcol = gcolBase + nt * 8;
                if (r0 < n)
                    *(__half2*)(g_xh + (size_t)r0 * 256 + gcol) =
                        __floats2half2_rn(c[mt][nt][0], c[mt][nt][1]);
                if (r1 < n)
                    *(__half2*)(g_xh + (size_t)r1 * 256 + gcol) =
                        __floats2half2_rn(c[mt][nt][2], c[mt][nt][3]);
            }
        }
    }
}

// ---------------- fused aggregate + update (paired fp16 gather, direct edge loads) ----------------
// one warp per node; 16 lanes cover a 256B xw half-row (uint4 each); 2 edges per LDG.128;
// each half-warp loads its own edge descriptor (no shuffles)
__global__ __launch_bounds__(256) void agg_update(const float* __restrict__ xin,
                                                  float* __restrict__ xout,
                                                  const float* __restrict__ bias,
                                                  int n) {
    int node = (blockIdx.x * blockDim.x + threadIdx.x) >> 5;
    int lane = threadIdx.x & 31;
    if (node >= n) return;

    int start = g_rowptr[node];
    int end = g_rowptr[node + 1];

    int sub = lane & 15;     // 16B chunk within xw half-row
    int hi = lane >> 4;      // 0: even edge of pair, 1: odd edge

    const uint4* xq = (const uint4*)g_xh;   // row r: [0..15]=xa, [16..31]=xw

    float acc[8];
#pragma unroll
    for (int q = 0; q < 8; q++) acc[q] = 0.f;

    // 4 pairs (8 edges) per step, zero-weight padding; no shuffles
    for (int t = start; t < end; t += 8) {
        int myc[4];
        float myw[4];
#pragma unroll
        for (int p = 0; p < 4; p++) {
            int idx = t + 2 * p + hi;
            int2 eb = make_int2(0, 0);
            if (idx < end) eb = __ldg(&g_edge[idx]);
            myc[p] = eb.x;
            myw[p] = __int_as_float(eb.y);
        }
        uint4 u[4];
#pragma unroll
        for (int p = 0; p < 4; p++)
            u[p] = __ldg(&xq[(size_t)myc[p] * 32 + 16 + sub]);
#pragma unroll
        for (int p = 0; p < 4; p++) {
            float2 f0 = __half22float2(*(__half2*)&u[p].x);
            float2 f1 = __half22float2(*(__half2*)&u[p].y);
            float2 f2 = __half22float2(*(__half2*)&u[p].z);
            float2 f3 = __half22float2(*(__half2*)&u[p].w);
            acc[0] += myw[p] * f0.x; acc[1] += myw[p] * f0.y;
            acc[2] += myw[p] * f1.x; acc[3] += myw[p] * f1.y;
            acc[4] += myw[p] * f2.x; acc[5] += myw[p] * f2.y;
            acc[6] += myw[p] * f3.x; acc[7] += myw[p] * f3.y;
        }
    }

    // combine even/odd-edge partials
#pragma unroll
    for (int q = 0; q < 8; q++) acc[q] += __shfl_xor_sync(0xFFFFFFFFu, acc[q], 16);

    // epilogue: lanes 0..15 own 8 cols each (cols sub*8 .. sub*8+7)
    if (hi == 0) {
        float dv = g_dinv[node];
        float d2 = dv * dv;

        uint4 ua = __ldg(&xq[(size_t)node * 32 + sub]);        // xa (fp16)
        uint4 us = __ldg(&xq[(size_t)node * 32 + 16 + sub]);   // xw self (fp16)
        float2 a0 = __half22float2(*(__half2*)&ua.x);
        float2 a1 = __half22float2(*(__half2*)&ua.y);
        float2 a2 = __half22float2(*(__half2*)&ua.z);
        float2 a3 = __half22float2(*(__half2*)&ua.w);
        float2 s0 = __half22float2(*(__half2*)&us.x);
        float2 s1 = __half22float2(*(__half2*)&us.y);
        float2 s2 = __half22float2(*(__half2*)&us.z);
        float2 s3 = __half22float2(*(__half2*)&us.w);
        float xa[8] = {a0.x, a0.y, a1.x, a1.y, a2.x, a2.y, a3.x, a3.y};
        float self[8] = {s0.x, s0.y, s1.x, s1.y, s2.x, s2.y, s3.x, s3.y};

        const float4* xv4 = (const float4*)(xin + (size_t)node * D) + sub * 2;
        const float4* bv4 = (const float4*)bias + sub * 2;
        float4* out4 = (float4*)(xout + (size_t)node * D) + sub * 2;

#pragma unroll
        for (int h = 0; h < 2; h++) {
            float4 xv = __ldg(&xv4[h]);
            float4 bv = __ldg(&bv4[h]);
            float4 o;
            o.x = xv.x + EPS * tanh_fast(xa[h * 4 + 0] + acc[h * 4 + 0] + self[h * 4 + 0] * d2 + bv.x);
            o.y = xv.y + EPS * tanh_fast(xa[h * 4 + 1] + acc[h * 4 + 1] + self[h * 4 + 1] * d2 + bv.y);
            o.z = xv.z + EPS * tanh_fast(xa[h * 4 + 2] + acc[h * 4 + 2] + self[h * 4 + 2] * d2 + bv.z);
            o.w = xv.w + EPS * tanh_fast(xa[h * 4 + 3] + acc[h * 4 + 3] + self[h * 4 + 3] * d2 + bv.w);
            out4[h] = o;
        }
    }
}

// ---------------- launch ----------------
extern "C" void kernel_launch(void* const* d_in, const int* in_sizes, int n_in,
                              void* d_out, int out_size) {
    const float* x0   = (const float*)d_in[0];
    const int*   ei   = (const int*)d_in[1];
    const float* W    = (const float*)d_in[2];
    const float* Wphi = (const float*)d_in[3];
    const float* bias = (const float*)d_in[4];

    int n = in_sizes[0] / D;
    int e = in_sizes[1] / 2;
    if (n > MAXN) n = MAXN;
    if (e > MAXE) e = MAXE;

    float* xbuf = nullptr;
    cudaGetSymbolAddress((void**)&xbuf, g_xbuf);
    float* outp = (float*)d_out;

    cudaFuncSetAttribute(gemm_mma, cudaFuncAttributeMaxDynamicSharedMemorySize, GEMM_SMEM);

    // one-time graph preprocessing
    prep_weights<<<(256 * D + 255) / 256, 256>>>(W, Wphi);
    zero_deg<<<(n + 255) / 256, 256>>>(n);
    count_deg<<<(e + 255) / 256, 256>>>(ei, e);
    int nb = (n + SCAN_BS - 1) / SCAN_BS;
    scan1<<<nb, SCAN_BS>>>(n);
    scan2<<<1, 1>>>(nb, e, n);
    scan3<<<(n + 255) / 256, 256>>>(n);
    fill_csr<<<(e + 255) / 256, 256>>>(ei, e);

    // 4 iterations, ping-pong: x0 -> xbuf -> d_out -> xbuf -> d_out
    const float* xin = x0;
    int tiles = (n + 127) >> 7;
    for (int it = 0; it < 4; it++) {
        float* xout = (it % 2 == 0) ? xbuf : outp;
        gemm_mma<<<148, GT, GEMM_SMEM>>>(xin, n, tiles);
        agg_update<<<(n + 7) / 8, 256>>>(xin, xout, bias, n);
        xin = xout;
    }
}

// round 11
// speedup vs baseline: 1.1594x; 1.0498x over previous
#include <cuda_runtime.h>
#include <cuda_fp16.h>
#include <math.h>
#include <stdint.h>

#define D 128
#define GAMMA 0.1f
#define EPS 0.1f
#define MAXN 100000
#define MAXE 1600000
#define SCAN_BS 1024
#define MAXB ((MAXN + SCAN_BS - 1) / SCAN_BS)

// ---------------- scratch (static device globals; no allocation) ----------------
__device__ __align__(16) __half g_xh[MAXN * 256];    // row: [xa (128) | xw (128)] fp16
__device__ __align__(16) float  g_xbuf[MAXN * D];    // ping-pong x buffer
__device__ __align__(16) float  g_wcat[256 * D];     // row j<128: A row j; j>=128: Wphi row j-128
__device__ int   g_deg[MAXN];
__device__ float g_dinv[MAXN];
__device__ int   g_rowptr[MAXN + 1];
__device__ int   g_wptr[MAXN];
__device__ __align__(8) int2 g_edge[MAXE];           // .x = src col, .y = norm (float bits)
__device__ int   g_bsums[MAXB + 2];
__device__ int   g_boff[MAXB + 2];

__device__ __forceinline__ float tanh_fast(float x) {
    float r;
    asm("tanh.approx.f32 %0, %1;" : "=f"(r) : "f"(x));
    return r;
}

// streaming (evict-first) accesses — keep g_xh resident in L2
__device__ __forceinline__ float4 ld_cs_f4(const float4* p) {
    float4 v;
    asm volatile("ld.global.cs.v4.f32 {%0,%1,%2,%3}, [%4];"
                 : "=f"(v.x), "=f"(v.y), "=f"(v.z), "=f"(v.w) : "l"(p));
    return v;
}
__device__ __forceinline__ void st_cs_f4(float4* p, float4 v) {
    asm volatile("st.global.cs.v4.f32 [%0], {%1,%2,%3,%4};"
                 :: "l"(p), "f"(v.x), "f"(v.y), "f"(v.z), "f"(v.w) : "memory");
}
__device__ __forceinline__ int2 ld_cs_i2(const int2* p) {
    int2 v;
    asm volatile("ld.global.cs.v2.s32 {%0,%1}, [%2];"
                 : "=r"(v.x), "=r"(v.y) : "l"(p));
    return v;
}

// ---------------- prep: build concatenated weight (row-major [j][k]) ----------------
__global__ void prep_weights(const float* __restrict__ W, const float* __restrict__ Wphi) {
    int idx = blockIdx.x * blockDim.x + threadIdx.x;
    if (idx >= 256 * D) return;
    int j = idx / D;
    int k = idx % D;
    float v;
    if (j < D) {
        v = W[j * D + k] - W[k * D + j];
        if (j == k) v -= GAMMA;
    } else {
        v = Wphi[(j - D) * D + k];
    }
    g_wcat[j * D + k] = v;
}

// ---------------- degree ----------------
__global__ void zero_deg(int n) {
    int i = blockIdx.x * blockDim.x + threadIdx.x;
    if (i < n) g_deg[i] = 0;
}
__global__ void count_deg(const int* __restrict__ ei, int e) {
    int idx = blockIdx.x * blockDim.x + threadIdx.x;
    if (idx >= e) return;
    atomicAdd(&g_deg[ei[e + idx]], 1);
}

// ---------------- exclusive scan of deg -> rowptr ----------------
__global__ void scan1(int n) {
    __shared__ int sh[SCAN_BS];
    int tx = threadIdx.x;
    int i = blockIdx.x * SCAN_BS + tx;
    int v = (i < n) ? g_deg[i] : 0;
    sh[tx] = v;
    __syncthreads();
    for (int off = 1; off < SCAN_BS; off <<= 1) {
        int t = (tx >= off) ? sh[tx - off] : 0;
        __syncthreads();
        sh[tx] += t;
        __syncthreads();
    }
    int incl = sh[tx];
    if (i < n) g_rowptr[i] = incl - v;
    if (tx == SCAN_BS - 1) g_bsums[blockIdx.x] = incl;
}
__global__ void scan2(int nb, int e_total, int n) {
    int run = 0;
    for (int b = 0; b < nb; b++) { g_boff[b] = run; run += g_bsums[b]; }
    g_rowptr[n] = e_total;
}
// scan3 also computes dinv (deg already loaded here)
__global__ void scan3(int n) {
    int i = blockIdx.x * blockDim.x + threadIdx.x;
    if (i >= n) return;
    int v = g_rowptr[i] + g_boff[i / SCAN_BS];
    g_rowptr[i] = v;
    g_wptr[i] = v;
    g_dinv[i] = rsqrtf((float)g_deg[i] + 1.0f);
}
__global__ void fill_csr(const int* __restrict__ ei, int e) {
    int idx = blockIdx.x * blockDim.x + threadIdx.x;
    if (idx >= e) return;
    int src = ei[idx];
    int dst = ei[e + idx];
    int pos = atomicAdd(&g_wptr[dst], 1);
    float nrm = g_dinv[src] * g_dinv[dst];
    g_edge[pos] = make_int2(src, __float_as_int(nrm));
}

// ---------------- tf32 mma.sync GEMM (persistent): [xa | xw] = x @ wcat^T ----------------
#define GT 512
#define LDP 132
#define GEMM_SMEM ((128 * LDP + 256 * LDP) * 4)

__device__ __forceinline__ uint32_t f2tf32(float f) {
    uint32_t u;
    asm("cvt.rna.tf32.f32 %0, %1;" : "=r"(u) : "f"(f));
    return u;
}

__global__ __launch_bounds__(GT, 1) void gemm_mma(const float* __restrict__ xin, int n, int tiles) {
    extern __shared__ float sm[];
    float* As = sm;               // 128 x 132
    float* Bs = sm + 128 * LDP;   // 256 x 132

    int tid = threadIdx.x;
    int wid = tid >> 5;
    int lane = tid & 31;

    // load B (weights) ONCE, tf32-rounded (RNA)
    for (int i = tid; i < 256 * 32; i += GT) {
        int j = i >> 5, c4 = i & 31;
        float4 v = ((const float4*)g_wcat)[i];
        float* dst = Bs + j * LDP + c4 * 4;
        dst[0] = __uint_as_float(f2tf32(v.x));
        dst[1] = __uint_as_float(f2tf32(v.y));
        dst[2] = __uint_as_float(f2tf32(v.z));
        dst[3] = __uint_as_float(f2tf32(v.w));
    }

    int wm = wid >> 2;
    int wn = wid & 3;
    int grp = lane >> 2;
    int tig = lane & 3;

    uint32_t As_base = (uint32_t)__cvta_generic_to_shared(As);

    const float* Abase = As + (wm * 32 + grp) * LDP + tig;
    const float* Bbase = Bs + (wn * 64 + grp) * LDP + tig;
    int gcolBase = (wn >= 2 ? 128 : 0) + (wn & 1) * 64 + 2 * tig;

    for (int t = blockIdx.x; t < tiles; t += gridDim.x) {
        int rowBase = t << 7;

        __syncthreads();

        // async-load A tile: 128 rows x 128 cols fp32 (zero-fill OOB rows)
#pragma unroll
        for (int i = tid; i < 4096; i += GT) {
            int r = i >> 5, c4 = i & 31;
            int row = rowBase + r;
            uint32_t daddr = As_base + (uint32_t)(r * LDP + c4 * 4) * 4u;
            const float* src = xin + (size_t)row * D + c4 * 4;
            int sz = (row < n) ? 16 : 0;
            asm volatile("cp.async.ca.shared.global [%0], [%1], 16, %2;"
                         :: "r"(daddr), "l"(src), "r"(sz));
        }
        asm volatile("cp.async.commit_group;");
        asm volatile("cp.async.wait_group 0;");
        __syncthreads();

        float c[2][8][4];
#pragma unroll
        for (int mt = 0; mt < 2; mt++)
#pragma unroll
            for (int nt = 0; nt < 8; nt++)
#pragma unroll
                for (int q = 0; q < 4; q++) c[mt][nt][q] = 0.f;

#pragma unroll
        for (int ks = 0; ks < 16; ks++) {
            int k0 = ks * 8;
            uint32_t a[2][4], b[8][2];
#pragma unroll
            for (int mt = 0; mt < 2; mt++) {
                const float* ap = Abase + mt * 16 * LDP + k0;
                a[mt][0] = __float_as_uint(ap[0]);
                a[mt][1] = __float_as_uint(ap[8 * LDP]);
                a[mt][2] = __float_as_uint(ap[4]);
                a[mt][3] = __float_as_uint(ap[8 * LDP + 4]);
            }
#pragma unroll
            for (int nt = 0; nt < 8; nt++) {
                const float* bp = Bbase + nt * 8 * LDP + k0;
                b[nt][0] = __float_as_uint(bp[0]);
                b[nt][1] = __float_as_uint(bp[4]);
            }
#pragma unroll
            for (int mt = 0; mt < 2; mt++) {
#pragma unroll
                for (int nt = 0; nt < 8; nt++) {
                    asm volatile(
                        "mma.sync.aligned.m16n8k8.row.col.f32.tf32.tf32.f32 "
                        "{%0,%1,%2,%3}, {%4,%5,%6,%7}, {%8,%9}, {%0,%1,%2,%3};"
                        : "+f"(c[mt][nt][0]), "+f"(c[mt][nt][1]),
                          "+f"(c[mt][nt][2]), "+f"(c[mt][nt][3])
                        : "r"(a[mt][0]), "r"(a[mt][1]), "r"(a[mt][2]), "r"(a[mt][3]),
                          "r"(b[nt][0]), "r"(b[nt][1]));
                }
            }
        }

        // epilogue: fp16 into combined [xa | xw] row
#pragma unroll
        for (int mt = 0; mt < 2; mt++) {
            int r0 = rowBase + wm * 32 + mt * 16 + grp;
            int r1 = r0 + 8;
#pragma unroll
            for (int nt = 0; nt < 8; nt++) {
                int gcol = gcolBase + nt * 8;
                if (r0 < n)
                    *(__half2*)(g_xh + (size_t)r0 * 256 + gcol) =
                        __floats2half2_rn(c[mt][nt][0], c[mt][nt][1]);
                if (r1 < n)
                    *(__half2*)(g_xh + (size_t)r1 * 256 + gcol) =
                        __floats2half2_rn(c[mt][nt][2], c[mt][nt][3]);
            }
        }
    }
}

// ---------------- fused aggregate + update (R6 shape + streaming hints) ----------------
// one warp per node; 16 lanes cover a 256B xw half-row (uint4 each); 2 edges per LDG.128
__global__ __launch_bounds__(256) void agg_update(const float* __restrict__ xin,
                                                  float* __restrict__ xout,
                                                  const float* __restrict__ bias,
                                                  int n) {
    int node = (blockIdx.x * blockDim.x + threadIdx.x) >> 5;
    int lane = threadIdx.x & 31;
    if (node >= n) return;

    int start = g_rowptr[node];
    int end = g_rowptr[node + 1];

    int sub = lane & 15;
    int hi = lane >> 4;

    const uint4* xq = (const uint4*)g_xh;   // row r: [0..15]=xa, [16..31]=xw

    float acc[8];
#pragma unroll
    for (int q = 0; q < 8; q++) acc[q] = 0.f;

    for (int j = start; j < end; j += 32) {
        int cnt = min(32, end - j);
        int c = 0;
        float w = 0.f;
        if (lane < cnt) {
            int2 eb = ld_cs_i2(&g_edge[j + lane]);   // streaming: don't evict g_xh
            c = eb.x;
            w = __int_as_float(eb.y);
        }
        int t = 0;
        // 4 pairs (8 edges) per step -> 4 independent LDG.128
        for (; t + 8 <= cnt; t += 8) {
            int myc[4];
            float myw[4];
#pragma unroll
            for (int p = 0; p < 4; p++) {
                int cl = __shfl_sync(0xFFFFFFFFu, c, t + 2 * p);
                int ch = __shfl_sync(0xFFFFFFFFu, c, t + 2 * p + 1);
                float wl = __shfl_sync(0xFFFFFFFFu, w, t + 2 * p);
                float wh = __shfl_sync(0xFFFFFFFFu, w, t + 2 * p + 1);
                myc[p] = hi ? ch : cl;
                myw[p] = hi ? wh : wl;
            }
            uint4 u[4];
#pragma unroll
            for (int p = 0; p < 4; p++)
                u[p] = __ldg(&xq[(size_t)myc[p] * 32 + 16 + sub]);
#pragma unroll
            for (int p = 0; p < 4; p++) {
                float2 f0 = __half22float2(*(__half2*)&u[p].x);
                float2 f1 = __half22float2(*(__half2*)&u[p].y);
                float2 f2 = __half22float2(*(__half2*)&u[p].z);
                float2 f3 = __half22float2(*(__half2*)&u[p].w);
                acc[0] += myw[p] * f0.x; acc[1] += myw[p] * f0.y;
                acc[2] += myw[p] * f1.x; acc[3] += myw[p] * f1.y;
                acc[4] += myw[p] * f2.x; acc[5] += myw[p] * f2.y;
                acc[6] += myw[p] * f3.x; acc[7] += myw[p] * f3.y;
            }
        }
        // remainder pairs
        for (; t < cnt; t += 2) {
            int cl = __shfl_sync(0xFFFFFFFFu, c, t);
            float wl = __shfl_sync(0xFFFFFFFFu, w, t);
            int ch = cl;
            float wh = 0.f;
            if (t + 1 < cnt) {
                ch = __shfl_sync(0xFFFFFFFFu, c, t + 1);
                wh = __shfl_sync(0xFFFFFFFFu, w, t + 1);
            }
            int myc = hi ? ch : cl;
            float myw = hi ? wh : wl;
            uint4 u = __ldg(&xq[(size_t)myc * 32 + 16 + sub]);
            float2 f0 = __half22float2(*(__half2*)&u.x);
            float2 f1 = __half22float2(*(__half2*)&u.y);
            float2 f2 = __half22float2(*(__half2*)&u.z);
            float2 f3 = __half22float2(*(__half2*)&u.w);
            acc[0] += myw * f0.x; acc[1] += myw * f0.y;
            acc[2] += myw * f1.x; acc[3] += myw * f1.y;
            acc[4] += myw * f2.x; acc[5] += myw * f2.y;
            acc[6] += myw * f3.x; acc[7] += myw * f3.y;
        }
    }

#pragma unroll
    for (int q = 0; q < 8; q++) acc[q] += __shfl_xor_sync(0xFFFFFFFFu, acc[q], 16);

    if (hi == 0) {
        float dv = g_dinv[node];
        float d2 = dv * dv;

        uint4 ua = __ldg(&xq[(size_t)node * 32 + sub]);        // xa (fp16, hot)
        uint4 us = __ldg(&xq[(size_t)node * 32 + 16 + sub]);   // xw self (fp16, hot)
        float2 a0 = __half22float2(*(__half2*)&ua.x);
        float2 a1 = __half22float2(*(__half2*)&ua.y);
        float2 a2 = __half22float2(*(__half2*)&ua.z);
        float2 a3 = __half22float2(*(__half2*)&ua.w);
        float2 s0 = __half22float2(*(__half2*)&us.x);
        float2 s1 = __half22float2(*(__half2*)&us.y);
        float2 s2 = __half22float2(*(__half2*)&us.z);
        float2 s3 = __half22float2(*(__half2*)&us.w);
        float xa[8] = {a0.x, a0.y, a1.x, a1.y, a2.x, a2.y, a3.x, a3.y};
        float self[8] = {s0.x, s0.y, s1.x, s1.y, s2.x, s2.y, s3.x, s3.y};

        const float4* xv4 = (const float4*)(xin + (size_t)node * D) + sub * 2;
        const float4* bv4 = (const float4*)bias + sub * 2;
        float4* out4 = (float4*)(xout + (size_t)node * D) + sub * 2;

#pragma unroll
        for (int h = 0; h < 2; h++) {
            float4 xv = ld_cs_f4(&xv4[h]);     // streaming
            float4 bv = __ldg(&bv4[h]);
            float4 o;
            o.x = xv.x + EPS * tanh_fast(xa[h * 4 + 0] + acc[h * 4 + 0] + self[h * 4 + 0] * d2 + bv.x);
            o.y = xv.y + EPS * tanh_fast(xa[h * 4 + 1] + acc[h * 4 + 1] + self[h * 4 + 1] * d2 + bv.y);
            o.z = xv.z + EPS * tanh_fast(xa[h * 4 + 2] + acc[h * 4 + 2] + self[h * 4 + 2] * d2 + bv.z);
            o.w = xv.w + EPS * tanh_fast(xa[h * 4 + 3] + acc[h * 4 + 3] + self[h * 4 + 3] * d2 + bv.w);
            st_cs_f4(&out4[h], o);             // streaming
        }
    }
}

// ---------------- launch ----------------
extern "C" void kernel_launch(void* const* d_in, const int* in_sizes, int n_in,
                              void* d_out, int out_size) {
    const float* x0   = (const float*)d_in[0];
    const int*   ei   = (const int*)d_in[1];
    const float* W    = (const float*)d_in[2];
    const float* Wphi = (const float*)d_in[3];
    const float* bias = (const float*)d_in[4];

    int n = in_sizes[0] / D;
    int e = in_sizes[1] / 2;
    if (n > MAXN) n = MAXN;
    if (e > MAXE) e = MAXE;

    float* xbuf = nullptr;
    cudaGetSymbolAddress((void**)&xbuf, g_xbuf);
    float* outp = (float*)d_out;

    cudaFuncSetAttribute(gemm_mma, cudaFuncAttributeMaxDynamicSharedMemorySize, GEMM_SMEM);

    // one-time graph preprocessing
    prep_weights<<<(256 * D + 255) / 256, 256>>>(W, Wphi);
    zero_deg<<<(n + 255) / 256, 256>>>(n);
    count_deg<<<(e + 255) / 256, 256>>>(ei, e);
    int nb = (n + SCAN_BS - 1) / SCAN_BS;
    scan1<<<nb, SCAN_BS>>>(n);
    scan2<<<1, 1>>>(nb, e, n);
    scan3<<<(n + 255) / 256, 256>>>(n);
    fill_csr<<<(e + 255) / 256, 256>>>(ei, e);

    // 4 iterations, ping-pong: x0 -> xbuf -> d_out -> xbuf -> d_out
    const float* xin = x0;
    int tiles = (n + 127) >> 7;
    for (int it = 0; it < 4; it++) {
        float* xout = (it % 2 == 0) ? xbuf : outp;
        gemm_mma<<<148, GT, GEMM_SMEM>>>(xin, n, tiles);
        agg_update<<<(n + 7) / 8, 256>>>(xin, xout, bias, n);
        xin = xout;
    }
}

// round 14
// speedup vs baseline: 1.3100x; 1.1298x over previous
#include <cuda_runtime.h>
#include <cuda_fp16.h>
#include <math.h>
#include <stdint.h>

#define D 128
#define GAMMA 0.1f
#define EPS 0.1f
#define MAXN 100000
#define MAXE 1600000
#define SCAN_BS 1024
#define MAXB ((MAXN + SCAN_BS - 1) / SCAN_BS)

// ---------------- scratch (static device globals; no allocation) ----------------
__device__ __align__(16) __half g_xh[MAXN * 256];    // row: [xa (128) | xw (128)] fp16
__device__ __align__(16) __half g_x16[MAXN * D];     // iterated state x (fp16, updated in place)
__device__ __align__(16) float  g_wcat[256 * D];     // row j<128: A row j; j>=128: Wphi row j-128
__device__ int   g_deg[MAXN];
__device__ float g_dinv[MAXN];
__device__ int   g_rowptr[MAXN + 1];
__device__ int   g_wptr[MAXN];
__device__ __align__(8) int2 g_edge[MAXE];           // .x = src col, .y = norm (float bits)
__device__ int   g_bsums[MAXB + 2];
__device__ int   g_boff[MAXB + 2];

__device__ __forceinline__ float tanh_fast(float x) {
    float r;
    asm("tanh.approx.f32 %0, %1;" : "=f"(r) : "f"(x));
    return r;
}

// streaming (evict-first) accesses — keep hot buffers resident in L2
__device__ __forceinline__ float4 ld_cs_f4(const float4* p) {
    float4 v;
    asm volatile("ld.global.cs.v4.f32 {%0,%1,%2,%3}, [%4];"
                 : "=f"(v.x), "=f"(v.y), "=f"(v.z), "=f"(v.w) : "l"(p));
    return v;
}
__device__ __forceinline__ void st_cs_f4(float4* p, float4 v) {
    asm volatile("st.global.cs.v4.f32 [%0], {%1,%2,%3,%4};"
                 :: "l"(p), "f"(v.x), "f"(v.y), "f"(v.z), "f"(v.w) : "memory");
}
__device__ __forceinline__ int2 ld_cs_i2(const int2* p) {
    int2 v;
    asm volatile("ld.global.cs.v2.s32 {%0,%1}, [%2];"
                 : "=r"(v.x), "=r"(v.y) : "l"(p));
    return v;
}

// ---------------- prep: build concatenated weight (row-major [j][k]) ----------------
__global__ void prep_weights(const float* __restrict__ W, const float* __restrict__ Wphi) {
    int idx = blockIdx.x * blockDim.x + threadIdx.x;
    if (idx >= 256 * D) return;
    int j = idx / D;
    int k = idx % D;
    float v;
    if (j < D) {
        v = W[j * D + k] - W[k * D + j];
        if (j == k) v -= GAMMA;
    } else {
        v = Wphi[(j - D) * D + k];
    }
    g_wcat[j * D + k] = v;
}

// ---------------- convert x0 -> fp16 state ----------------
__global__ void conv_x(const float* __restrict__ x0, int n) {
    int i = blockIdx.x * blockDim.x + threadIdx.x;
    if (i >= n * 32) return;            // n*128/4 float4s
    float4 v = ld_cs_f4(&((const float4*)x0)[i]);
    __half2 p0 = __floats2half2_rn(v.x, v.y);
    __half2 p1 = __floats2half2_rn(v.z, v.w);
    uint2 h;
    h.x = *(uint32_t*)&p0;
    h.y = *(uint32_t*)&p1;
    ((uint2*)g_x16)[i] = h;
}

// ---------------- degree ----------------
__global__ void zero_deg(int n) {
    int i = blockIdx.x * blockDim.x + threadIdx.x;
    if (i < n) g_deg[i] = 0;
}
__global__ void count_deg(const int* __restrict__ ei, int e) {
    int idx = blockIdx.x * blockDim.x + threadIdx.x;
    if (idx >= e) return;
    atomicAdd(&g_deg[ei[e + idx]], 1);
}

// ---------------- exclusive scan of deg -> rowptr ----------------
__global__ void scan1(int n) {
    __shared__ int sh[SCAN_BS];
    int tx = threadIdx.x;
    int i = blockIdx.x * SCAN_BS + tx;
    int v = (i < n) ? g_deg[i] : 0;
    sh[tx] = v;
    __syncthreads();
    for (int off = 1; off < SCAN_BS; off <<= 1) {
        int t = (tx >= off) ? sh[tx - off] : 0;
        __syncthreads();
        sh[tx] += t;
        __syncthreads();
    }
    int incl = sh[tx];
    if (i < n) g_rowptr[i] = incl - v;
    if (tx == SCAN_BS - 1) g_bsums[blockIdx.x] = incl;
}
__global__ void scan2(int nb, int e_total, int n) {
    int run = 0;
    for (int b = 0; b < nb; b++) { g_boff[b] = run; run += g_bsums[b]; }
    g_rowptr[n] = e_total;
}
__global__ void scan3(int n) {
    int i = blockIdx.x * blockDim.x + threadIdx.x;
    if (i >= n) return;
    int v = g_rowptr[i] + g_boff[i / SCAN_BS];
    g_rowptr[i] = v;
    g_wptr[i] = v;
    g_dinv[i] = rsqrtf((float)g_deg[i] + 1.0f);
}
__global__ void fill_csr(const int* __restrict__ ei, int e) {
    int idx = blockIdx.x * blockDim.x + threadIdx.x;
    if (idx >= e) return;
    int src = ei[idx];
    int dst = ei[e + idx];
    int pos = atomicAdd(&g_wptr[dst], 1);
    float nrm = g_dinv[src] * g_dinv[dst];
    g_edge[pos] = make_int2(src, __float_as_int(nrm));
}

// ---------------- fp16 mma.sync GEMM (persistent): [xa | xw] = x @ wcat^T ----------------
// grid = 148 persistent CTAs, 512 threads (16 warps, 4x4). tile 128 rows x 256 cols, K=128.
// m16n8k16 f16 HMMA with fp32 accumulators. A and B fp16 in SMEM (LDH=136 halfs/row pad).
#define GT 512
#define LDH 136
#define GEMM_SMEM ((128 * LDH + 256 * LDH) * 2)

__global__ __launch_bounds__(GT, 1) void gemm_mma(int n, int tiles) {
    extern __shared__ __half smh[];
    __half* As = smh;                  // 128 x 136
    __half* Bs = smh + 128 * LDH;      // 256 x 136

    int tid = threadIdx.x;
    int wid = tid >> 5;
    int lane = tid & 31;

    // load B (weights) ONCE, fp32 -> fp16
    for (int i = tid; i < 256 * 32; i += GT) {
        int j = i >> 5, c4 = i & 31;
        float4 v = ((const float4*)g_wcat)[i];
        __half2 p0 = __floats2half2_rn(v.x, v.y);
        __half2 p1 = __floats2half2_rn(v.z, v.w);
        *(__half2*)(Bs + j * LDH + c4 * 4) = p0;
        *(__half2*)(Bs + j * LDH + c4 * 4 + 2) = p1;
    }

    int wm = wid >> 2;
    int wn = wid & 3;
    int grp = lane >> 2;
    int tig = lane & 3;

    uint32_t As_base = (uint32_t)__cvta_generic_to_shared(As);

    const __half* Ab = As + (wm * 32 + grp) * LDH + 2 * tig;
    const __half* Bb = Bs + (wn * 64 + grp) * LDH + 2 * tig;
    int gcolBase = (wn >= 2 ? 128 : 0) + (wn & 1) * 64 + 2 * tig;

    for (int t = blockIdx.x; t < tiles; t += gridDim.x) {
        int rowBase = t << 7;

        __syncthreads();

        // async-load A tile: 128 rows x 128 halfs = 2048 16B chunks (zero-fill OOB rows)
#pragma unroll
        for (int i = tid; i < 2048; i += GT) {
            int r = i >> 4, c16 = i & 15;
            int row = rowBase + r;
            uint32_t daddr = As_base + (uint32_t)(r * LDH + c16 * 8) * 2u;
            const __half* src = g_x16 + (size_t)row * D + c16 * 8;
            int sz = (row < n) ? 16 : 0;
            asm volatile("cp.async.ca.shared.global [%0], [%1], 16, %2;"
                         :: "r"(daddr), "l"(src), "r"(sz));
        }
        asm volatile("cp.async.commit_group;");
        asm volatile("cp.async.wait_group 0;");
        __syncthreads();

        float c[2][8][4];
#pragma unroll
        for (int mt = 0; mt < 2; mt++)
#pragma unroll
            for (int nt = 0; nt < 8; nt++)
#pragma unroll
                for (int q = 0; q < 4; q++) c[mt][nt][q] = 0.f;

#pragma unroll
        for (int ks = 0; ks < 8; ks++) {
            int k0 = ks * 16;
            uint32_t a[2][4], b[8][2];
#pragma unroll
            for (int mt = 0; mt < 2; mt++) {
                const __half* ap = Ab + mt * 16 * LDH + k0;
                a[mt][0] = *(const uint32_t*)(ap);
                a[mt][1] = *(const uint32_t*)(ap + 8 * LDH);
                a[mt][2] = *(const uint32_t*)(ap + 8);
                a[mt][3] = *(const uint32_t*)(ap + 8 * LDH + 8);
            }
#pragma unroll
            for (int nt = 0; nt < 8; nt++) {
                const __half* bp = Bb + nt * 8 * LDH + k0;
                b[nt][0] = *(const uint32_t*)(bp);
                b[nt][1] = *(const uint32_t*)(bp + 8);
            }
#pragma unroll
            for (int mt = 0; mt < 2; mt++) {
#pragma unroll
                for (int nt = 0; nt < 8; nt++) {
                    asm volatile(
                        "mma.sync.aligned.m16n8k16.row.col.f32.f16.f16.f32 "
                        "{%0,%1,%2,%3}, {%4,%5,%6,%7}, {%8,%9}, {%0,%1,%2,%3};"
                        : "+f"(c[mt][nt][0]), "+f"(c[mt][nt][1]),
                          "+f"(c[mt][nt][2]), "+f"(c[mt][nt][3])
                        : "r"(a[mt][0]), "r"(a[mt][1]), "r"(a[mt][2]), "r"(a[mt][3]),
                          "r"(b[nt][0]), "r"(b[nt][1]));
                }
            }
        }

        // epilogue: fp16 into combined [xa | xw] row
#pragma unroll
        for (int mt = 0; mt < 2; mt++) {
            int r0 = rowBase + wm * 32 + mt * 16 + grp;
            int r1 = r0 + 8;
#pragma unroll
            for (int nt = 0; nt < 8; nt++) {
                int gcol = gcolBase + nt * 8;
                if (r0 < n)
                    *(__half2*)(g_xh + (size_t)r0 * 256 + gcol) =
                        __floats2half2_rn(c[mt][nt][0], c[mt][nt][1]);
                if (r1 < n)
                    *(__half2*)(g_xh + (size_t)r1 * 256 + gcol) =
                        __floats2half2_rn(c[mt][nt][2], c[mt][nt][3]);
            }
        }
    }
}

// ---------------- fused aggregate + update (R6 gather shape, fp16 x in place) ----------------
// one warp per node; 16 lanes cover a 256B xw half-row (uint4 each); 2 edges per LDG.128
// x32 non-null on iter 0 (fp32 residual source); fout non-null on last iter (fp32 output)
__global__ __launch_bounds__(256) void agg_update(const float* __restrict__ x32,
                                                  float* __restrict__ fout,
                                                  const float* __restrict__ bias,
                                                  int n) {
    int node = (blockIdx.x * blockDim.x + threadIdx.x) >> 5;
    int lane = threadIdx.x & 31;
    if (node >= n) return;

    int start = g_rowptr[node];
    int end = g_rowptr[node + 1];

    int sub = lane & 15;
    int hi = lane >> 4;

    const uint4* xq = (const uint4*)g_xh;   // row r: [0..15]=xa, [16..31]=xw

    float acc[8];
#pragma unroll
    for (int q = 0; q < 8; q++) acc[q] = 0.f;

    for (int j = start; j < end; j += 32) {
        int cnt = min(32, end - j);
        int c = 0;
        float w = 0.f;
        if (lane < cnt) {
            int2 eb = ld_cs_i2(&g_edge[j + lane]);   // streaming
            c = eb.x;
            w = __int_as_float(eb.y);
        }
        int t = 0;
        for (; t + 8 <= cnt; t += 8) {
            int myc[4];
            float myw[4];
#pragma unroll
            for (int p = 0; p < 4; p++) {
                int cl = __shfl_sync(0xFFFFFFFFu, c, t + 2 * p);
                int ch = __shfl_sync(0xFFFFFFFFu, c, t + 2 * p + 1);
                float wl = __shfl_sync(0xFFFFFFFFu, w, t + 2 * p);
                float wh = __shfl_sync(0xFFFFFFFFu, w, t + 2 * p + 1);
                myc[p] = hi ? ch : cl;
                myw[p] = hi ? wh : wl;
            }
            uint4 u[4];
#pragma unroll
            for (int p = 0; p < 4; p++)
                u[p] = __ldg(&xq[(size_t)myc[p] * 32 + 16 + sub]);
#pragma unroll
            for (int p = 0; p < 4; p++) {
                float2 f0 = __half22float2(*(__half2*)&u[p].x);
                float2 f1 = __half22float2(*(__half2*)&u[p].y);
                float2 f2 = __half22float2(*(__half2*)&u[p].z);
                float2 f3 = __half22float2(*(__half2*)&u[p].w);
                acc[0] += myw[p] * f0.x; acc[1] += myw[p] * f0.y;
                acc[2] += myw[p] * f1.x; acc[3] += myw[p] * f1.y;
                acc[4] += myw[p] * f2.x; acc[5] += myw[p] * f2.y;
                acc[6] += myw[p] * f3.x; acc[7] += myw[p] * f3.y;
            }
        }
        for (; t < cnt; t += 2) {
            int cl = __shfl_sync(0xFFFFFFFFu, c, t);
            float wl = __shfl_sync(0xFFFFFFFFu, w, t);
            int ch = cl;
            float wh = 0.f;
            if (t + 1 < cnt) {
                ch = __shfl_sync(0xFFFFFFFFu, c, t + 1);
                wh = __shfl_sync(0xFFFFFFFFu, w, t + 1);
            }
            int myc = hi ? ch : cl;
            float myw = hi ? wh : wl;
            uint4 u = __ldg(&xq[(size_t)myc * 32 + 16 + sub]);
            float2 f0 = __half22float2(*(__half2*)&u.x);
            float2 f1 = __half22float2(*(__half2*)&u.y);
            float2 f2 = __half22float2(*(__half2*)&u.z);
            float2 f3 = __half22float2(*(__half2*)&u.w);
            acc[0] += myw * f0.x; acc[1] += myw * f0.y;
            acc[2] += myw * f1.x; acc[3] += myw * f1.y;
            acc[4] += myw * f2.x; acc[5] += myw * f2.y;
            acc[6] += myw * f3.x; acc[7] += myw * f3.y;
        }
    }

#pragma unroll
    for (int q = 0; q < 8; q++) acc[q] += __shfl_xor_sync(0xFFFFFFFFu, acc[q], 16);

    if (hi == 0) {
        float dv = g_dinv[node];
        float d2 = dv * dv;

        uint4 ua = __ldg(&xq[(size_t)node * 32 + sub]);        // xa (fp16, hot)
        uint4 us = __ldg(&xq[(size_t)node * 32 + 16 + sub]);   // xw self (fp16, hot)
        float2 a0 = __half22float2(*(__half2*)&ua.x);
        float2 a1 = __half22float2(*(__half2*)&ua.y);
        float2 a2 = __half22float2(*(__half2*)&ua.z);
        float2 a3 = __half22float2(*(__half2*)&ua.w);
        float2 s0 = __half22float2(*(__half2*)&us.x);
        float2 s1 = __half22float2(*(__half2*)&us.y);
        float2 s2 = __half22float2(*(__half2*)&us.z);
        float2 s3 = __half22float2(*(__half2*)&us.w);
        float xa[8] = {a0.x, a0.y, a1.x, a1.y, a2.x, a2.y, a3.x, a3.y};
        float self[8] = {s0.x, s0.y, s1.x, s1.y, s2.x, s2.y, s3.x, s3.y};

        // residual x: fp32 source on iter 0, else in-place fp16 state
        float xv[8];
        if (x32) {
            const float4* xv4 = (const float4*)(x32 + (size_t)node * D) + sub * 2;
            float4 v0 = ld_cs_f4(&xv4[0]);
            float4 v1 = ld_cs_f4(&xv4[1]);
            xv[0] = v0.x; xv[1] = v0.y; xv[2] = v0.z; xv[3] = v0.w;
            xv[4] = v1.x; xv[5] = v1.y; xv[6] = v1.z; xv[7] = v1.w;
        } else {
            uint4 ux = __ldg(&((const uint4*)g_x16)[(size_t)node * 16 + sub]);
            float2 x0f = __half22float2(*(__half2*)&ux.x);
            float2 x1f = __half22float2(*(__half2*)&ux.y);
            float2 x2f = __half22float2(*(__half2*)&ux.z);
            float2 x3f = __half22float2(*(__half2*)&ux.w);
            xv[0] = x0f.x; xv[1] = x0f.y; xv[2] = x1f.x; xv[3] = x1f.y;
            xv[4] = x2f.x; xv[5] = x2f.y; xv[6] = x3f.x; xv[7] = x3f.y;
        }

        const float4* bv4 = (const float4*)bias + sub * 2;
        float4 bv0 = __ldg(&bv4[0]);
        float4 bv1 = __ldg(&bv4[1]);
        float bv[8] = {bv0.x, bv0.y, bv0.z, bv0.w, bv1.x, bv1.y, bv1.z, bv1.w};

        float o[8];
#pragma unroll
        for (int q = 0; q < 8; q++)
            o[q] = xv[q] + EPS * tanh_fast(xa[q] + acc[q] + self[q] * d2 + bv[q]);

        if (fout) {
            float4* out4 = (float4*)(fout + (size_t)node * D) + sub * 2;
            st_cs_f4(&out4[0], make_float4(o[0], o[1], o[2], o[3]));
            st_cs_f4(&out4[1], make_float4(o[4], o[5], o[6], o[7]));
        } else {
            __half2 p0 = __floats2half2_rn(o[0], o[1]);
            __half2 p1 = __floats2half2_rn(o[2], o[3]);
            __half2 p2 = __floats2half2_rn(o[4], o[5]);
            __half2 p3 = __floats2half2_rn(o[6], o[7]);
            uint4 hv;
            hv.x = *(uint32_t*)&p0;
            hv.y = *(uint32_t*)&p1;
            hv.z = *(uint32_t*)&p2;
            hv.w = *(uint32_t*)&p3;
            ((uint4*)g_x16)[(size_t)node * 16 + sub] = hv;
        }
    }
}

// ---------------- launch ----------------
extern "C" void kernel_launch(void* const* d_in, const int* in_sizes, int n_in,
                              void* d_out, int out_size) {
    const float* x0   = (const float*)d_in[0];
    const int*   ei   = (const int*)d_in[1];
    const float* W    = (const float*)d_in[2];
    const float* Wphi = (const float*)d_in[3];
    const float* bias = (const float*)d_in[4];

    int n = in_sizes[0] / D;
    int e = in_sizes[1] / 2;
    if (n > MAXN) n = MAXN;
    if (e > MAXE) e = MAXE;

    float* outp = (float*)d_out;

    cudaFuncSetAttribute(gemm_mma, cudaFuncAttributeMaxDynamicSharedMemorySize, GEMM_SMEM);

    // one-time graph preprocessing
    prep_weights<<<(256 * D + 255) / 256, 256>>>(W, Wphi);
    zero_deg<<<(n + 255) / 256, 256>>>(n);
    count_deg<<<(e + 255) / 256, 256>>>(ei, e);
    int nb = (n + SCAN_BS - 1) / SCAN_BS;
    scan1<<<nb, SCAN_BS>>>(n);
    scan2<<<1, 1>>>(nb, e, n);
    scan3<<<(n + 255) / 256, 256>>>(n);
    fill_csr<<<(e + 255) / 256, 256>>>(ei, e);
    conv_x<<<(n * 32 + 255) / 256, 256>>>(x0, n);

    // 4 iterations; x lives in g_x16 (fp16, in place); final iter writes fp32 d_out
    int tiles = (n + 127) >> 7;
    for (int it = 0; it < 4; it++) {
        gemm_mma<<<148, GT, GEMM_SMEM>>>(n, tiles);
        agg_update<<<(n + 7) / 8, 256>>>((it == 0) ? x0 : nullptr,
                                         (it == 3) ? outp : nullptr,
                                         bias, n);
    }
}

// round 15
// speedup vs baseline: 1.5072x; 1.1506x over previous
#include <cuda_runtime.h>
#include <cuda_fp16.h>
#include <math.h>
#include <stdint.h>

#define D 128
#define GAMMA 0.1f
#define EPS 0.1f
#define MAXN 100000
#define MAXE 1600000
#define SCAN_BS 1024
#define MAXB ((MAXN + SCAN_BS - 1) / SCAN_BS)

// ---------------- scratch (static device globals; no allocation) ----------------
__device__ __align__(16) __half g_xh[MAXN * 256];    // row: [xa (128) | xw*dinv (128)] fp16
__device__ __align__(16) __half g_x16[MAXN * D];     // iterated state x (fp16, in place)
__device__ __align__(16) float  g_wcat[256 * D];     // row j<128: A row j; j>=128: Wphi row j-128
__device__ int   g_deg[MAXN];
__device__ float g_dinv[MAXN];
__device__ int   g_rowptr[MAXN + 1];
__device__ int   g_wptr[MAXN];
__device__ int   g_ecol[MAXE];                       // src index only (norm folded into rows)
__device__ int   g_bsums[MAXB + 2];
__device__ int   g_boff[MAXB + 2];

__device__ __forceinline__ float tanh_fast(float x) {
    float r;
    asm("tanh.approx.f32 %0, %1;" : "=f"(r) : "f"(x));
    return r;
}

// streaming (evict-first) accesses — keep hot buffers resident in L2
__device__ __forceinline__ float4 ld_cs_f4(const float4* p) {
    float4 v;
    asm volatile("ld.global.cs.v4.f32 {%0,%1,%2,%3}, [%4];"
                 : "=f"(v.x), "=f"(v.y), "=f"(v.z), "=f"(v.w) : "l"(p));
    return v;
}
__device__ __forceinline__ void st_cs_f4(float4* p, float4 v) {
    asm volatile("st.global.cs.v4.f32 [%0], {%1,%2,%3,%4};"
                 :: "l"(p), "f"(v.x), "f"(v.y), "f"(v.z), "f"(v.w) : "memory");
}
__device__ __forceinline__ int ld_cs_i(const int* p) {
    int v;
    asm volatile("ld.global.cs.s32 %0, [%1];" : "=r"(v) : "l"(p));
    return v;
}

// ---------------- prep: build concatenated weight (row-major [j][k]) ----------------
__global__ void prep_weights(const float* __restrict__ W, const float* __restrict__ Wphi) {
    int idx = blockIdx.x * blockDim.x + threadIdx.x;
    if (idx >= 256 * D) return;
    int j = idx / D;
    int k = idx % D;
    float v;
    if (j < D) {
        v = W[j * D + k] - W[k * D + j];
        if (j == k) v -= GAMMA;
    } else {
        v = Wphi[(j - D) * D + k];
    }
    g_wcat[j * D + k] = v;
}

// ---------------- convert x0 -> fp16 state ----------------
__global__ void conv_x(const float* __restrict__ x0, int n) {
    int i = blockIdx.x * blockDim.x + threadIdx.x;
    if (i >= n * 32) return;            // n*128/4 float4s
    float4 v = ld_cs_f4(&((const float4*)x0)[i]);
    __half2 p0 = __floats2half2_rn(v.x, v.y);
    __half2 p1 = __floats2half2_rn(v.z, v.w);
    uint2 h;
    h.x = *(uint32_t*)&p0;
    h.y = *(uint32_t*)&p1;
    ((uint2*)g_x16)[i] = h;
}

// ---------------- degree ----------------
__global__ void zero_deg(int n) {
    int i = blockIdx.x * blockDim.x + threadIdx.x;
    if (i < n) g_deg[i] = 0;
}
__global__ void count_deg(const int* __restrict__ ei, int e) {
    int idx = blockIdx.x * blockDim.x + threadIdx.x;
    if (idx >= e) return;
    atomicAdd(&g_deg[ei[e + idx]], 1);
}

// ---------------- exclusive scan of deg -> rowptr ----------------
__global__ void scan1(int n) {
    __shared__ int sh[SCAN_BS];
    int tx = threadIdx.x;
    int i = blockIdx.x * SCAN_BS + tx;
    int v = (i < n) ? g_deg[i] : 0;
    sh[tx] = v;
    __syncthreads();
    for (int off = 1; off < SCAN_BS; off <<= 1) {
        int t = (tx >= off) ? sh[tx - off] : 0;
        __syncthreads();
        sh[tx] += t;
        __syncthreads();
    }
    int incl = sh[tx];
    if (i < n) g_rowptr[i] = incl - v;
    if (tx == SCAN_BS - 1) g_bsums[blockIdx.x] = incl;
}
__global__ void scan2(int nb, int e_total, int n) {
    int run = 0;
    for (int b = 0; b < nb; b++) { g_boff[b] = run; run += g_bsums[b]; }
    g_rowptr[n] = e_total;
}
__global__ void scan3(int n) {
    int i = blockIdx.x * blockDim.x + threadIdx.x;
    if (i >= n) return;
    int v = g_rowptr[i] + g_boff[i / SCAN_BS];
    g_rowptr[i] = v;
    g_wptr[i] = v;
    g_dinv[i] = rsqrtf((float)g_deg[i] + 1.0f);
}
__global__ void fill_csr(const int* __restrict__ ei, int e) {
    int idx = blockIdx.x * blockDim.x + threadIdx.x;
    if (idx >= e) return;
    int src = ei[idx];
    int dst = ei[e + idx];
    int pos = atomicAdd(&g_wptr[dst], 1);
    g_ecol[pos] = src;
}

// ---------------- fp16 mma.sync GEMM (persistent): [xa | xw*dinv] = x @ wcat^T ----------------
// grid = 148 persistent CTAs, 512 threads (16 warps, 4x4). tile 128 rows x 256 cols, K=128.
#define GT 512
#define LDH 136
#define GEMM_SMEM ((128 * LDH + 256 * LDH) * 2)

__global__ __launch_bounds__(GT, 1) void gemm_mma(int n, int tiles) {
    extern __shared__ __half smh[];
    __half* As = smh;                  // 128 x 136
    __half* Bs = smh + 128 * LDH;      // 256 x 136

    int tid = threadIdx.x;
    int wid = tid >> 5;
    int lane = tid & 31;

    // load B (weights) ONCE, fp32 -> fp16
    for (int i = tid; i < 256 * 32; i += GT) {
        int j = i >> 5, c4 = i & 31;
        float4 v = ((const float4*)g_wcat)[i];
        __half2 p0 = __floats2half2_rn(v.x, v.y);
        __half2 p1 = __floats2half2_rn(v.z, v.w);
        *(__half2*)(Bs + j * LDH + c4 * 4) = p0;
        *(__half2*)(Bs + j * LDH + c4 * 4 + 2) = p1;
    }

    int wm = wid >> 2;
    int wn = wid & 3;
    int grp = lane >> 2;
    int tig = lane & 3;

    uint32_t As_base = (uint32_t)__cvta_generic_to_shared(As);

    const __half* Ab = As + (wm * 32 + grp) * LDH + 2 * tig;
    const __half* Bb = Bs + (wn * 64 + grp) * LDH + 2 * tig;
    int isXW = (wn >= 2);
    int gcolBase = (isXW ? 128 : 0) + (wn & 1) * 64 + 2 * tig;

    for (int t = blockIdx.x; t < tiles; t += gridDim.x) {
        int rowBase = t << 7;

        __syncthreads();

        // async-load A tile: 128 rows x 128 halfs = 2048 16B chunks (zero-fill OOB rows)
#pragma unroll
        for (int i = tid; i < 2048; i += GT) {
            int r = i >> 4, c16 = i & 15;
            int row = rowBase + r;
            uint32_t daddr = As_base + (uint32_t)(r * LDH + c16 * 8) * 2u;
            const __half* src = g_x16 + (size_t)row * D + c16 * 8;
            int sz = (row < n) ? 16 : 0;
            asm volatile("cp.async.ca.shared.global [%0], [%1], 16, %2;"
                         :: "r"(daddr), "l"(src), "r"(sz));
        }
        asm volatile("cp.async.commit_group;");
        asm volatile("cp.async.wait_group 0;");
        __syncthreads();

        float c[2][8][4];
#pragma unroll
        for (int mt = 0; mt < 2; mt++)
#pragma unroll
            for (int nt = 0; nt < 8; nt++)
#pragma unroll
                for (int q = 0; q < 4; q++) c[mt][nt][q] = 0.f;

#pragma unroll
        for (int ks = 0; ks < 8; ks++) {
            int k0 = ks * 16;
            uint32_t a[2][4], b[8][2];
#pragma unroll
            for (int mt = 0; mt < 2; mt++) {
                const __half* ap = Ab + mt * 16 * LDH + k0;
                a[mt][0] = *(const uint32_t*)(ap);
                a[mt][1] = *(const uint32_t*)(ap + 8 * LDH);
                a[mt][2] = *(const uint32_t*)(ap + 8);
                a[mt][3] = *(const uint32_t*)(ap + 8 * LDH + 8);
            }
#pragma unroll
            for (int nt = 0; nt < 8; nt++) {
                const __half* bp = Bb + nt * 8 * LDH + k0;
                b[nt][0] = *(const uint32_t*)(bp);
                b[nt][1] = *(const uint32_t*)(bp + 8);
            }
#pragma unroll
            for (int mt = 0; mt < 2; mt++) {
#pragma unroll
                for (int nt = 0; nt < 8; nt++) {
                    asm volatile(
                        "mma.sync.aligned.m16n8k16.row.col.f32.f16.f16.f32 "
                        "{%0,%1,%2,%3}, {%4,%5,%6,%7}, {%8,%9}, {%0,%1,%2,%3};"
                        : "+f"(c[mt][nt][0]), "+f"(c[mt][nt][1]),
                          "+f"(c[mt][nt][2]), "+f"(c[mt][nt][3])
                        : "r"(a[mt][0]), "r"(a[mt][1]), "r"(a[mt][2]), "r"(a[mt][3]),
                          "r"(b[nt][0]), "r"(b[nt][1]));
                }
            }
        }

        // epilogue: xa unscaled; xw scaled by dinv[row] (folds edge norm)
#pragma unroll
        for (int mt = 0; mt < 2; mt++) {
            int r0 = rowBase + wm * 32 + mt * 16 + grp;
            int r1 = r0 + 8;
            float s0 = 1.f, s1 = 1.f;
            if (isXW) {
                if (r0 < n) s0 = g_dinv[r0];
                if (r1 < n) s1 = g_dinv[r1];
            }
#pragma unroll
            for (int nt = 0; nt < 8; nt++) {
                int gcol = gcolBase + nt * 8;
                if (r0 < n)
                    *(__half2*)(g_xh + (size_t)r0 * 256 + gcol) =
                        __floats2half2_rn(c[mt][nt][0] * s0, c[mt][nt][1] * s0);
                if (r1 < n)
                    *(__half2*)(g_xh + (size_t)r1 * 256 + gcol) =
                        __floats2half2_rn(c[mt][nt][2] * s1, c[mt][nt][3] * s1);
            }
        }
    }
}

// ---------------- fused aggregate + update (unweighted gather, dinv folded) ----------------
// one warp per node; 16 lanes cover a 256B xw half-row (uint4 each); 2 edges per LDG.128
__global__ __launch_bounds__(256) void agg_update(const float* __restrict__ x32,
                                                  float* __restrict__ fout,
                                                  const float* __restrict__ bias,
                                                  int n) {
    int node = (blockIdx.x * blockDim.x + threadIdx.x) >> 5;
    int lane = threadIdx.x & 31;
    if (node >= n) return;

    int start = g_rowptr[node];
    int end = g_rowptr[node + 1];

    int sub = lane & 15;
    int hi = lane >> 4;

    const uint4* xq = (const uint4*)g_xh;   // row r: [0..15]=xa, [16..31]=xw*dinv

    float acc[8];
#pragma unroll
    for (int q = 0; q < 8; q++) acc[q] = 0.f;

    for (int j = start; j < end; j += 32) {
        int cnt = min(32, end - j);
        int c = 0;
        if (lane < cnt) c = ld_cs_i(&g_ecol[j + lane]);   // streaming
        int t = 0;
        // 4 pairs (8 edges) per step -> 4 independent LDG.128; pure adds
        for (; t + 8 <= cnt; t += 8) {
            int myc[4];
#pragma unroll
            for (int p = 0; p < 4; p++) {
                int cl = __shfl_sync(0xFFFFFFFFu, c, t + 2 * p);
                int ch = __shfl_sync(0xFFFFFFFFu, c, t + 2 * p + 1);
                myc[p] = hi ? ch : cl;
            }
            uint4 u[4];
#pragma unroll
            for (int p = 0; p < 4; p++)
                u[p] = __ldg(&xq[(size_t)myc[p] * 32 + 16 + sub]);
#pragma unroll
            for (int p = 0; p < 4; p++) {
                float2 f0 = __half22float2(*(__half2*)&u[p].x);
                float2 f1 = __half22float2(*(__half2*)&u[p].y);
                float2 f2 = __half22float2(*(__half2*)&u[p].z);
                float2 f3 = __half22float2(*(__half2*)&u[p].w);
                acc[0] += f0.x; acc[1] += f0.y;
                acc[2] += f1.x; acc[3] += f1.y;
                acc[4] += f2.x; acc[5] += f2.y;
                acc[6] += f3.x; acc[7] += f3.y;
            }
        }
        // remainder pairs (0/1 weight, no loads)
        for (; t < cnt; t += 2) {
            int s = t + hi;
            int cc = __shfl_sync(0xFFFFFFFFu, c, min(s, 31));
            float ww = (s < cnt) ? 1.f : 0.f;
            uint4 u = __ldg(&xq[(size_t)cc * 32 + 16 + sub]);
            float2 f0 = __half22float2(*(__half2*)&u.x);
            float2 f1 = __half22float2(*(__half2*)&u.y);
            float2 f2 = __half22float2(*(__half2*)&u.z);
            float2 f3 = __half22float2(*(__half2*)&u.w);
            acc[0] += ww * f0.x; acc[1] += ww * f0.y;
            acc[2] += ww * f1.x; acc[3] += ww * f1.y;
            acc[4] += ww * f2.x; acc[5] += ww * f2.y;
            acc[6] += ww * f3.x; acc[7] += ww * f3.y;
        }
    }

#pragma unroll
    for (int q = 0; q < 8; q++) acc[q] += __shfl_xor_sync(0xFFFFFFFFu, acc[q], 16);

    if (hi == 0) {
        float dv = g_dinv[node];

        uint4 ua = __ldg(&xq[(size_t)node * 32 + sub]);        // xa (fp16, hot)
        uint4 us = __ldg(&xq[(size_t)node * 32 + 16 + sub]);   // xw*dinv self (fp16, hot)
        float2 a0 = __half22float2(*(__half2*)&ua.x);
        float2 a1 = __half22float2(*(__half2*)&ua.y);
        float2 a2 = __half22float2(*(__half2*)&ua.z);
        float2 a3 = __half22float2(*(__half2*)&ua.w);
        float2 s0 = __half22float2(*(__half2*)&us.x);
        float2 s1 = __half22float2(*(__half2*)&us.y);
        float2 s2 = __half22float2(*(__half2*)&us.z);
        float2 s3 = __half22float2(*(__half2*)&us.w);
        float xa[8] = {a0.x, a0.y, a1.x, a1.y, a2.x, a2.y, a3.x, a3.y};
        float self[8] = {s0.x, s0.y, s1.x, s1.y, s2.x, s2.y, s3.x, s3.y};

        // residual x: fp32 source on iter 0, else in-place fp16 state
        float xv[8];
        if (x32) {
            const float4* xv4 = (const float4*)(x32 + (size_t)node * D) + sub * 2;
            float4 v0 = ld_cs_f4(&xv4[0]);
            float4 v1 = ld_cs_f4(&xv4[1]);
            xv[0] = v0.x; xv[1] = v0.y; xv[2] = v0.z; xv[3] = v0.w;
            xv[4] = v1.x; xv[5] = v1.y; xv[6] = v1.z; xv[7] = v1.w;
        } else {
            uint4 ux = __ldg(&((const uint4*)g_x16)[(size_t)node * 16 + sub]);
            float2 x0f = __half22float2(*(__half2*)&ux.x);
            float2 x1f = __half22float2(*(__half2*)&ux.y);
            float2 x2f = __half22float2(*(__half2*)&ux.z);
            float2 x3f = __half22float2(*(__half2*)&ux.w);
            xv[0] = x0f.x; xv[1] = x0f.y; xv[2] = x1f.x; xv[3] = x1f.y;
            xv[4] = x2f.x; xv[5] = x2f.y; xv[6] = x3f.x; xv[7] = x3f.y;
        }

        const float4* bv4 = (const float4*)bias + sub * 2;
        float4 bv0 = __ldg(&bv4[0]);
        float4 bv1 = __ldg(&bv4[1]);
        float bv[8] = {bv0.x, bv0.y, bv0.z, bv0.w, bv1.x, bv1.y, bv1.z, bv1.w};

        float o[8];
#pragma unroll
        for (int q = 0; q < 8; q++)
            o[q] = xv[q] + EPS * tanh_fast(xa[q] + dv * (acc[q] + self[q]) + bv[q]);

        if (fout) {
            float4* out4 = (float4*)(fout + (size_t)node * D) + sub * 2;
            st_cs_f4(&out4[0], make_float4(o[0], o[1], o[2], o[3]));
            st_cs_f4(&out4[1], make_float4(o[4], o[5], o[6], o[7]));
        } else {
            __half2 p0 = __floats2half2_rn(o[0], o[1]);
            __half2 p1 = __floats2half2_rn(o[2], o[3]);
            __half2 p2 = __floats2half2_rn(o[4], o[5]);
            __half2 p3 = __floats2half2_rn(o[6], o[7]);
            uint4 hv;
            hv.x = *(uint32_t*)&p0;
            hv.y = *(uint32_t*)&p1;
            hv.z = *(uint32_t*)&p2;
            hv.w = *(uint32_t*)&p3;
            ((uint4*)g_x16)[(size_t)node * 16 + sub] = hv;
        }
    }
}

// ---------------- launch ----------------
extern "C" void kernel_launch(void* const* d_in, const int* in_sizes, int n_in,
                              void* d_out, int out_size) {
    const float* x0   = (const float*)d_in[0];
    const int*   ei   = (const int*)d_in[1];
    const float* W    = (const float*)d_in[2];
    const float* Wphi = (const float*)d_in[3];
    const float* bias = (const float*)d_in[4];

    int n = in_sizes[0] / D;
    int e = in_sizes[1] / 2;
    if (n > MAXN) n = MAXN;
    if (e > MAXE) e = MAXE;

    float* outp = (float*)d_out;

    cudaFuncSetAttribute(gemm_mma, cudaFuncAttributeMaxDynamicSharedMemorySize, GEMM_SMEM);

    // one-time graph preprocessing
    prep_weights<<<(256 * D + 255) / 256, 256>>>(W, Wphi);
    zero_deg<<<(n + 255) / 256, 256>>>(n);
    count_deg<<<(e + 255) / 256, 256>>>(ei, e);
    int nb = (n + SCAN_BS - 1) / SCAN_BS;
    scan1<<<nb, SCAN_BS>>>(n);
    scan2<<<1, 1>>>(nb, e, n);
    scan3<<<(n + 255) / 256, 256>>>(n);
    fill_csr<<<(e + 255) / 256, 256>>>(ei, e);
    conv_x<<<(n * 32 + 255) / 256, 256>>>(x0, n);

    // 4 iterations; x lives in g_x16 (fp16, in place); final iter writes fp32 d_out
    int tiles = (n + 127) >> 7;
    for (int it = 0; it < 4; it++) {
        gemm_mma<<<148, GT, GEMM_SMEM>>>(n, tiles);
        agg_update<<<(n + 7) / 8, 256>>>((it == 0) ? x0 : nullptr,
                                         (it == 3) ? outp : nullptr,
                                         bias, n);
    }
}

// round 16
// speedup vs baseline: 1.5298x; 1.0150x over previous
#include <cuda_runtime.h>
#include <cuda_fp16.h>
#include <math.h>
#include <stdint.h>

#define D 128
#define GAMMA 0.1f
#define EPS 0.1f
#define MAXN 100000
#define MAXE 1600000
#define SCAN_BS 1024
#define MAXB ((MAXN + SCAN_BS - 1) / SCAN_BS)

// ---------------- scratch (static device globals; no allocation) ----------------
__device__ __align__(16) __half g_xh[MAXN * 256];    // row: [xa (128) | xw*dinv (128)] fp16
__device__ __align__(16) __half g_x16[MAXN * D];     // iterated state x (fp16, in place)
__device__ __align__(16) float  g_wcat[256 * D];     // row j<128: A row j; j>=128: Wphi row j-128
__device__ int   g_deg[MAXN];
__device__ float g_dinv[MAXN];
__device__ int   g_rowptr[MAXN + 1];
__device__ int   g_wptr[MAXN];
__device__ int   g_ecol[MAXE];                       // src index only (norm folded into rows)
__device__ int   g_bsums[MAXB + 2];
__device__ int   g_boff[MAXB + 2];

__device__ __forceinline__ float tanh_fast(float x) {
    float r;
    asm("tanh.approx.f32 %0, %1;" : "=f"(r) : "f"(x));
    return r;
}

// streaming (evict-first) accesses — keep hot buffers resident in L2
__device__ __forceinline__ float4 ld_cs_f4(const float4* p) {
    float4 v;
    asm volatile("ld.global.cs.v4.f32 {%0,%1,%2,%3}, [%4];"
                 : "=f"(v.x), "=f"(v.y), "=f"(v.z), "=f"(v.w) : "l"(p));
    return v;
}
__device__ __forceinline__ void st_cs_f4(float4* p, float4 v) {
    asm volatile("st.global.cs.v4.f32 [%0], {%1,%2,%3,%4};"
                 :: "l"(p), "f"(v.x), "f"(v.y), "f"(v.z), "f"(v.w) : "memory");
}
__device__ __forceinline__ int ld_cs_i(const int* p) {
    int v;
    asm volatile("ld.global.cs.s32 %0, [%1];" : "=r"(v) : "l"(p));
    return v;
}

// ---------------- fused init: conv_x + prep_weights + zero_deg ----------------
__global__ void init_all(const float* __restrict__ x0,
                         const float* __restrict__ W,
                         const float* __restrict__ Wphi, int n) {
    int i = blockIdx.x * blockDim.x + threadIdx.x;
    // conv_x: n*32 float4 chunks
    if (i < n * 32) {
        float4 v = ld_cs_f4(&((const float4*)x0)[i]);
        __half2 p0 = __floats2half2_rn(v.x, v.y);
        __half2 p1 = __floats2half2_rn(v.z, v.w);
        uint2 h;
        h.x = *(uint32_t*)&p0;
        h.y = *(uint32_t*)&p1;
        ((uint2*)g_x16)[i] = h;
    }
    // prep_weights: 256*128 entries
    if (i < 256 * D) {
        int j = i / D;
        int k = i % D;
        float v;
        if (j < D) {
            v = W[j * D + k] - W[k * D + j];
            if (j == k) v -= GAMMA;
        } else {
            v = Wphi[(j - D) * D + k];
        }
        g_wcat[j * D + k] = v;
    }
    // zero_deg
    if (i < n) g_deg[i] = 0;
}

// ---------------- degree ----------------
__global__ void count_deg(const int* __restrict__ ei, int e) {
    int idx = blockIdx.x * blockDim.x + threadIdx.x;
    if (idx >= e) return;
    atomicAdd(&g_deg[ei[e + idx]], 1);
}

// ---------------- exclusive scan of deg -> rowptr ----------------
__global__ void scan1(int n) {
    __shared__ int sh[SCAN_BS];
    int tx = threadIdx.x;
    int i = blockIdx.x * SCAN_BS + tx;
    int v = (i < n) ? g_deg[i] : 0;
    sh[tx] = v;
    __syncthreads();
    for (int off = 1; off < SCAN_BS; off <<= 1) {
        int t = (tx >= off) ? sh[tx - off] : 0;
        __syncthreads();
        sh[tx] += t;
        __syncthreads();
    }
    int incl = sh[tx];
    if (i < n) g_rowptr[i] = incl - v;
    if (tx == SCAN_BS - 1) g_bsums[blockIdx.x] = incl;
}
__global__ void scan2(int nb, int e_total, int n) {
    int run = 0;
    for (int b = 0; b < nb; b++) { g_boff[b] = run; run += g_bsums[b]; }
    g_rowptr[n] = e_total;
}
__global__ void scan3(int n) {
    int i = blockIdx.x * blockDim.x + threadIdx.x;
    if (i >= n) return;
    int v = g_rowptr[i] + g_boff[i / SCAN_BS];
    g_rowptr[i] = v;
    g_wptr[i] = v;
    g_dinv[i] = rsqrtf((float)g_deg[i] + 1.0f);
}
__global__ void fill_csr(const int* __restrict__ ei, int e) {
    int idx = blockIdx.x * blockDim.x + threadIdx.x;
    if (idx >= e) return;
    int src = ei[idx];
    int dst = ei[e + idx];
    int pos = atomicAdd(&g_wptr[dst], 1);
    g_ecol[pos] = src;
}

// ---------------- fp16 mma.sync GEMM (persistent, 2-stage pipeline) ----------------
// grid = 148 persistent CTAs, 512 threads. tile 128 rows x 256 cols, K=128.
// SMEM: B (256x136) + 2 A stages (128x136 each), all fp16.
#define GT 512
#define LDH 136
#define A_STAGE (128 * LDH)
#define GEMM_SMEM ((256 * LDH + 2 * A_STAGE) * 2)

__device__ __forceinline__ void prefetch_A(uint32_t As_base, int rowBase, int n, int tid) {
#pragma unroll
    for (int i = tid; i < 2048; i += GT) {
        int r = i >> 4, c16 = i & 15;
        int row = rowBase + r;
        uint32_t daddr = As_base + (uint32_t)(r * LDH + c16 * 8) * 2u;
        const __half* src = g_x16 + (size_t)row * D + c16 * 8;
        int sz = (row < n) ? 16 : 0;
        asm volatile("cp.async.ca.shared.global [%0], [%1], 16, %2;"
                     :: "r"(daddr), "l"(src), "r"(sz));
    }
    asm volatile("cp.async.commit_group;");
}

__global__ __launch_bounds__(GT, 1) void gemm_mma(int n, int tiles) {
    extern __shared__ __half smh[];
    __half* Bs = smh;                    // 256 x 136
    __half* A0 = smh + 256 * LDH;        // stage 0
    __half* A1 = A0 + A_STAGE;           // stage 1

    int tid = threadIdx.x;
    int wid = tid >> 5;
    int lane = tid & 31;

    // load B (weights) ONCE, fp32 -> fp16
    for (int i = tid; i < 256 * 32; i += GT) {
        int j = i >> 5, c4 = i & 31;
        float4 v = ((const float4*)g_wcat)[i];
        __half2 p0 = __floats2half2_rn(v.x, v.y);
        __half2 p1 = __floats2half2_rn(v.z, v.w);
        *(__half2*)(Bs + j * LDH + c4 * 4) = p0;
        *(__half2*)(Bs + j * LDH + c4 * 4 + 2) = p1;
    }

    int wm = wid >> 2;
    int wn = wid & 3;
    int grp = lane >> 2;
    int tig = lane & 3;

    uint32_t A0_base = (uint32_t)__cvta_generic_to_shared(A0);
    uint32_t A1_base = (uint32_t)__cvta_generic_to_shared(A1);

    const __half* Bb = Bs + (wn * 64 + grp) * LDH + 2 * tig;
    int isXW = (wn >= 2);
    int gcolBase = (isXW ? 128 : 0) + (wn & 1) * 64 + 2 * tig;

    int t = blockIdx.x;
    int stage = 0;
    if (t < tiles) prefetch_A(A0_base, t << 7, n, tid);

    for (; t < tiles; t += gridDim.x) {
        int rowBase = t << 7;
        int tn = t + gridDim.x;
        if (tn < tiles)
            prefetch_A(stage ? A0_base : A1_base, tn << 7, n, tid);

        // wait for current stage (1 group may remain pending = the prefetch just issued)
        if (tn < tiles)
            asm volatile("cp.async.wait_group 1;");
        else
            asm volatile("cp.async.wait_group 0;");
        __syncthreads();

        const __half* Acur = stage ? A1 : A0;
        const __half* Ab = Acur + (wm * 32 + grp) * LDH + 2 * tig;

        float c[2][8][4];
#pragma unroll
        for (int mt = 0; mt < 2; mt++)
#pragma unroll
            for (int nt = 0; nt < 8; nt++)
#pragma unroll
                for (int q = 0; q < 4; q++) c[mt][nt][q] = 0.f;

#pragma unroll
        for (int ks = 0; ks < 8; ks++) {
            int k0 = ks * 16;
            uint32_t a[2][4], b[8][2];
#pragma unroll
            for (int mt = 0; mt < 2; mt++) {
                const __half* ap = Ab + mt * 16 * LDH + k0;
                a[mt][0] = *(const uint32_t*)(ap);
                a[mt][1] = *(const uint32_t*)(ap + 8 * LDH);
                a[mt][2] = *(const uint32_t*)(ap + 8);
                a[mt][3] = *(const uint32_t*)(ap + 8 * LDH + 8);
            }
#pragma unroll
            for (int nt = 0; nt < 8; nt++) {
                const __half* bp = Bb + nt * 8 * LDH + k0;
                b[nt][0] = *(const uint32_t*)(bp);
                b[nt][1] = *(const uint32_t*)(bp + 8);
            }
#pragma unroll
            for (int mt = 0; mt < 2; mt++) {
#pragma unroll
                for (int nt = 0; nt < 8; nt++) {
                    asm volatile(
                        "mma.sync.aligned.m16n8k16.row.col.f32.f16.f16.f32 "
                        "{%0,%1,%2,%3}, {%4,%5,%6,%7}, {%8,%9}, {%0,%1,%2,%3};"
                        : "+f"(c[mt][nt][0]), "+f"(c[mt][nt][1]),
                          "+f"(c[mt][nt][2]), "+f"(c[mt][nt][3])
                        : "r"(a[mt][0]), "r"(a[mt][1]), "r"(a[mt][2]), "r"(a[mt][3]),
                          "r"(b[nt][0]), "r"(b[nt][1]));
                }
            }
        }

        // epilogue: xa unscaled; xw scaled by dinv[row]
#pragma unroll
        for (int mt = 0; mt < 2; mt++) {
            int r0 = rowBase + wm * 32 + mt * 16 + grp;
            int r1 = r0 + 8;
            float s0 = 1.f, s1 = 1.f;
            if (isXW) {
                if (r0 < n) s0 = g_dinv[r0];
                if (r1 < n) s1 = g_dinv[r1];
            }
#pragma unroll
            for (int nt = 0; nt < 8; nt++) {
                int gcol = gcolBase + nt * 8;
                if (r0 < n)
                    *(__half2*)(g_xh + (size_t)r0 * 256 + gcol) =
                        __floats2half2_rn(c[mt][nt][0] * s0, c[mt][nt][1] * s0);
                if (r1 < n)
                    *(__half2*)(g_xh + (size_t)r1 * 256 + gcol) =
                        __floats2half2_rn(c[mt][nt][2] * s1, c[mt][nt][3] * s1);
            }
        }

        __syncthreads();   // all reads of current stage done before it's re-filled
        stage ^= 1;
    }
}

// ---------------- fused aggregate + update (unweighted gather, dinv folded) ----------------
__global__ __launch_bounds__(256) void agg_update(const float* __restrict__ x32,
                                                  float* __restrict__ fout,
                                                  const float* __restrict__ bias,
                                                  int n) {
    int node = (blockIdx.x * blockDim.x + threadIdx.x) >> 5;
    int lane = threadIdx.x & 31;
    if (node >= n) return;

    int start = g_rowptr[node];
    int end = g_rowptr[node + 1];

    int sub = lane & 15;
    int hi = lane >> 4;

    const uint4* xq = (const uint4*)g_xh;

    float acc[8];
#pragma unroll
    for (int q = 0; q < 8; q++) acc[q] = 0.f;

    for (int j = start; j < end; j += 32) {
        int cnt = min(32, end - j);
        int c = 0;
        if (lane < cnt) c = ld_cs_i(&g_ecol[j + lane]);
        int t = 0;
        for (; t + 8 <= cnt; t += 8) {
            int myc[4];
#pragma unroll
            for (int p = 0; p < 4; p++) {
                int cl = __shfl_sync(0xFFFFFFFFu, c, t + 2 * p);
                int ch = __shfl_sync(0xFFFFFFFFu, c, t + 2 * p + 1);
                myc[p] = hi ? ch : cl;
            }
            uint4 u[4];
#pragma unroll
            for (int p = 0; p < 4; p++)
                u[p] = __ldg(&xq[(size_t)myc[p] * 32 + 16 + sub]);
#pragma unroll
            for (int p = 0; p < 4; p++) {
                float2 f0 = __half22float2(*(__half2*)&u[p].x);
                float2 f1 = __half22float2(*(__half2*)&u[p].y);
                float2 f2 = __half22float2(*(__half2*)&u[p].z);
                float2 f3 = __half22float2(*(__half2*)&u[p].w);
                acc[0] += f0.x; acc[1] += f0.y;
                acc[2] += f1.x; acc[3] += f1.y;
                acc[4] += f2.x; acc[5] += f2.y;
                acc[6] += f3.x; acc[7] += f3.y;
            }
        }
        for (; t < cnt; t += 2) {
            int s = t + hi;
            int cc = __shfl_sync(0xFFFFFFFFu, c, min(s, 31));
            float ww = (s < cnt) ? 1.f : 0.f;
            uint4 u = __ldg(&xq[(size_t)cc * 32 + 16 + sub]);
            float2 f0 = __half22float2(*(__half2*)&u.x);
            float2 f1 = __half22float2(*(__half2*)&u.y);
            float2 f2 = __half22float2(*(__half2*)&u.z);
            float2 f3 = __half22float2(*(__half2*)&u.w);
            acc[0] += ww * f0.x; acc[1] += ww * f0.y;
            acc[2] += ww * f1.x; acc[3] += ww * f1.y;
            acc[4] += ww * f2.x; acc[5] += ww * f2.y;
            acc[6] += ww * f3.x; acc[7] += ww * f3.y;
        }
    }

#pragma unroll
    for (int q = 0; q < 8; q++) acc[q] += __shfl_xor_sync(0xFFFFFFFFu, acc[q], 16);

    if (hi == 0) {
        float dv = g_dinv[node];

        uint4 ua = __ldg(&xq[(size_t)node * 32 + sub]);
        uint4 us = __ldg(&xq[(size_t)node * 32 + 16 + sub]);
        float2 a0 = __half22float2(*(__half2*)&ua.x);
        float2 a1 = __half22float2(*(__half2*)&ua.y);
        float2 a2 = __half22float2(*(__half2*)&ua.z);
        float2 a3 = __half22float2(*(__half2*)&ua.w);
        float2 s0 = __half22float2(*(__half2*)&us.x);
        float2 s1 = __half22float2(*(__half2*)&us.y);
        float2 s2 = __half22float2(*(__half2*)&us.z);
        float2 s3 = __half22float2(*(__half2*)&us.w);
        float xa[8] = {a0.x, a0.y, a1.x, a1.y, a2.x, a2.y, a3.x, a3.y};
        float self[8] = {s0.x, s0.y, s1.x, s1.y, s2.x, s2.y, s3.x, s3.y};

        float xv[8];
        if (x32) {
            const float4* xv4 = (const float4*)(x32 + (size_t)node * D) + sub * 2;
            float4 v0 = ld_cs_f4(&xv4[0]);
            float4 v1 = ld_cs_f4(&xv4[1]);
            xv[0] = v0.x; xv[1] = v0.y; xv[2] = v0.z; xv[3] = v0.w;
            xv[4] = v1.x; xv[5] = v1.y; xv[6] = v1.z; xv[7] = v1.w;
        } else {
            uint4 ux = __ldg(&((const uint4*)g_x16)[(size_t)node * 16 + sub]);
            float2 x0f = __half22float2(*(__half2*)&ux.x);
            float2 x1f = __half22float2(*(__half2*)&ux.y);
            float2 x2f = __half22float2(*(__half2*)&ux.z);
            float2 x3f = __half22float2(*(__half2*)&ux.w);
            xv[0] = x0f.x; xv[1] = x0f.y; xv[2] = x1f.x; xv[3] = x1f.y;
            xv[4] = x2f.x; xv[5] = x2f.y; xv[6] = x3f.x; xv[7] = x3f.y;
        }

        const float4* bv4 = (const float4*)bias + sub * 2;
        float4 bv0 = __ldg(&bv4[0]);
        float4 bv1 = __ldg(&bv4[1]);
        float bv[8] = {bv0.x, bv0.y, bv0.z, bv0.w, bv1.x, bv1.y, bv1.z, bv1.w};

        float o[8];
#pragma unroll
        for (int q = 0; q < 8; q++)
            o[q] = xv[q] + EPS * tanh_fast(xa[q] + dv * (acc[q] + self[q]) + bv[q]);

        if (fout) {
            float4* out4 = (float4*)(fout + (size_t)node * D) + sub * 2;
            st_cs_f4(&out4[0], make_float4(o[0], o[1], o[2], o[3]));
            st_cs_f4(&out4[1], make_float4(o[4], o[5], o[6], o[7]));
        } else {
            __half2 p0 = __floats2half2_rn(o[0], o[1]);
            __half2 p1 = __floats2half2_rn(o[2], o[3]);
            __half2 p2 = __floats2half2_rn(o[4], o[5]);
            __half2 p3 = __floats2half2_rn(o[6], o[7]);
            uint4 hv;
            hv.x = *(uint32_t*)&p0;
            hv.y = *(uint32_t*)&p1;
            hv.z = *(uint32_t*)&p2;
            hv.w = *(uint32_t*)&p3;
            ((uint4*)g_x16)[(size_t)node * 16 + sub] = hv;
        }
    }
}

// ---------------- launch ----------------
extern "C" void kernel_launch(void* const* d_in, const int* in_sizes, int n_in,
                              void* d_out, int out_size) {
    const float* x0   = (const float*)d_in[0];
    const int*   ei   = (const int*)d_in[1];
    const float* W    = (const float*)d_in[2];
    const float* Wphi = (const float*)d_in[3];
    const float* bias = (const float*)d_in[4];

    int n = in_sizes[0] / D;
    int e = in_sizes[1] / 2;
    if (n > MAXN) n = MAXN;
    if (e > MAXE) e = MAXE;

    float* outp = (float*)d_out;

    cudaFuncSetAttribute(gemm_mma, cudaFuncAttributeMaxDynamicSharedMemorySize, GEMM_SMEM);

    // one-time graph preprocessing (fused init + CSR build)
    init_all<<<(n * 32 + 255) / 256, 256>>>(x0, W, Wphi, n);
    count_deg<<<(e + 255) / 256, 256>>>(ei, e);
    int nb = (n + SCAN_BS - 1) / SCAN_BS;
    scan1<<<nb, SCAN_BS>>>(n);
    scan2<<<1, 1>>>(nb, e, n);
    scan3<<<(n + 255) / 256, 256>>>(n);
    fill_csr<<<(e + 255) / 256, 256>>>(ei, e);

    // 4 iterations; x lives in g_x16 (fp16, in place); final iter writes fp32 d_out
    int tiles = (n + 127) >> 7;
    for (int it = 0; it < 4; it++) {
        gemm_mma<<<148, GT, GEMM_SMEM>>>(n, tiles);
        agg_update<<<(n + 7) / 8, 256>>>((it == 0) ? x0 : nullptr,
                                         (it == 3) ? outp : nullptr,
                                         bias, n);
    }
}